// round 1
// baseline (speedup 1.0000x reference)
#include <cuda_runtime.h>
#include <math.h>

#define B_ 4
#define N_ 2048
#define F_ 1024
#define H_ 16
#define D_ 64
#define M_ (B_*N_)   // 8192 rows

// Scratch for Q/K/V in [b, h, n, d] layout (32 MB each). __device__ globals are
// the sanctioned scratch mechanism (no cudaMalloc allowed).
__device__ float g_q[(size_t)B_*H_*N_*D_];
__device__ float g_k[(size_t)B_*H_*N_*D_];
__device__ float g_v[(size_t)B_*H_*N_*D_];

// ---------------------------------------------------------------------------
// QKV projection GEMM: out[b,h,n,d] = sum_k X[b*N+n, k] * W[k, h*D+d] + bias
// 128x128 block tile, K-tile 8, 256 threads, 8x8 register micro-tile.
// ---------------------------------------------------------------------------
__global__ __launch_bounds__(256, 2)
void qkv_gemm_kernel(const float* __restrict__ X,
                     const float* __restrict__ W,
                     const float* __restrict__ bias,
                     float* __restrict__ outp)
{
    __shared__ float As[8][128];   // As[k][m]
    __shared__ float Bs[8][128];   // Bs[k][n]

    const int tid = threadIdx.x;
    const int ty  = tid >> 4;          // 0..15
    const int tx  = tid & 15;          // 0..15
    const int m0  = blockIdx.y * 128;
    const int n0  = blockIdx.x * 128;

    // global-load assignments
    const int lm  = tid >> 1;          // 0..127 (row of X tile)
    const int lk  = (tid & 1) * 4;     // 0 or 4 (k quad)
    const int lbr = tid >> 5;          // 0..7   (row of W tile)
    const int lbc = (tid & 31) * 4;    // 0..124 (col quad of W tile)

    float acc[8][8];
#pragma unroll
    for (int i = 0; i < 8; i++)
#pragma unroll
        for (int j = 0; j < 8; j++) acc[i][j] = 0.f;

    const float* xp = X + (size_t)(m0 + lm) * F_ + lk;
    const float* wp = W + (size_t)lbr * F_ + n0 + lbc;

    for (int k0 = 0; k0 < F_; k0 += 8) {
        float4 xa = *(const float4*)(xp + k0);
        float4 wb = *(const float4*)(wp + (size_t)k0 * F_);
        __syncthreads();   // previous compute done before overwriting smem
        As[lk + 0][lm] = xa.x;
        As[lk + 1][lm] = xa.y;
        As[lk + 2][lm] = xa.z;
        As[lk + 3][lm] = xa.w;
        *(float4*)&Bs[lbr][lbc] = wb;
        __syncthreads();
#pragma unroll
        for (int kk = 0; kk < 8; kk++) {
            float4 a0 = *(float4*)&As[kk][ty * 8];
            float4 a1 = *(float4*)&As[kk][ty * 8 + 4];
            float4 b0 = *(float4*)&Bs[kk][tx * 8];
            float4 b1 = *(float4*)&Bs[kk][tx * 8 + 4];
            float a[8] = {a0.x, a0.y, a0.z, a0.w, a1.x, a1.y, a1.z, a1.w};
            float b[8] = {b0.x, b0.y, b0.z, b0.w, b1.x, b1.y, b1.z, b1.w};
#pragma unroll
            for (int i = 0; i < 8; i++)
#pragma unroll
                for (int j = 0; j < 8; j++)
                    acc[i][j] = fmaf(a[i], b[j], acc[i][j]);
        }
    }

    // epilogue: add bias, scatter into [b, h, n, d]
    const int bb    = m0 / N_;   // batch constant per block (2048 % 128 == 0)
    const int nbase = m0 % N_;
    float bias0[8];
    *(float4*)&bias0[0] = *(const float4*)&bias[n0 + tx * 8];
    *(float4*)&bias0[4] = *(const float4*)&bias[n0 + tx * 8 + 4];
    const int col0 = n0 + tx * 8;
    const int h  = col0 / D_;    // 8-col group never crosses a head (8 | 64)
    const int d0 = col0 % D_;

#pragma unroll
    for (int i = 0; i < 8; i++) {
        const int nq = nbase + ty * 8 + i;
        float* op = outp + (((size_t)(bb * H_ + h)) * N_ + nq) * D_ + d0;
        float4 r0 = make_float4(acc[i][0] + bias0[0], acc[i][1] + bias0[1],
                                acc[i][2] + bias0[2], acc[i][3] + bias0[3]);
        float4 r1 = make_float4(acc[i][4] + bias0[4], acc[i][5] + bias0[5],
                                acc[i][6] + bias0[6], acc[i][7] + bias0[7]);
        *(float4*)op       = r0;
        *(float4*)(op + 4) = r1;
    }
}

// ---------------------------------------------------------------------------
// Causal flash attention, fp32. One block = one (b,h) x 64-row Q tile.
// 256 threads as 16x16; each thread owns a 4x4 micro-tile of S / O.
// Online softmax with shuffle reductions across the 16 tx lanes.
// ---------------------------------------------------------------------------
__global__ __launch_bounds__(256, 2)
void flash_attn_kernel(const float* __restrict__ gq,
                       const float* __restrict__ gk,
                       const float* __restrict__ gv,
                       float* __restrict__ out)
{
    extern __shared__ float sm[];
    float* Qs = sm;               // [64][68]  Qs[d][r] (transposed, pre-scaled)
    float* Ks = Qs + 64 * 68;     // [64][68]  Ks[d][c] (transposed)
    float* Vs = Ks + 64 * 68;     // [64][68]  Vs[j][d] (natural)
    float* Pt = Vs + 64 * 68;     // [64][68]  Pt[r][c]

    const int tid = threadIdx.x;
    const int ty  = tid >> 4;     // 0..15
    const int tx  = tid & 15;     // 0..15
    const int qt  = blockIdx.x;   // 0..31 query tile
    const int bh  = blockIdx.y;   // 0..63 (b*H + h)
    const int n0  = qt * 64;

    const float* qbase = gq + (size_t)bh * N_ * D_;
    const float* kbase = gk + (size_t)bh * N_ * D_;
    const float* vbase = gv + (size_t)bh * N_ * D_;

    // load Q tile transposed, pre-scaled by 1/sqrt(D) = 0.125
    for (int c = tid; c < 64 * 16; c += 256) {
        int r  = c >> 4;
        int dq = (c & 15) << 2;
        float4 v = *(const float4*)(qbase + (size_t)(n0 + r) * D_ + dq);
        Qs[(dq + 0) * 68 + r] = v.x * 0.125f;
        Qs[(dq + 1) * 68 + r] = v.y * 0.125f;
        Qs[(dq + 2) * 68 + r] = v.z * 0.125f;
        Qs[(dq + 3) * 68 + r] = v.w * 0.125f;
    }

    float accO[4][4];
    float mrow[4], lrow[4];
#pragma unroll
    for (int i = 0; i < 4; i++) {
        mrow[i] = -1e30f;
        lrow[i] = 0.f;
#pragma unroll
        for (int j = 0; j < 4; j++) accO[i][j] = 0.f;
    }

    for (int kt = 0; kt <= qt; kt++) {
        const int c0 = kt * 64;
        __syncthreads();   // previous iteration finished with Ks/Vs/Pt
        for (int c = tid; c < 64 * 16; c += 256) {
            int r  = c >> 4;
            int dq = (c & 15) << 2;
            float4 kv = *(const float4*)(kbase + (size_t)(c0 + r) * D_ + dq);
            Ks[(dq + 0) * 68 + r] = kv.x;
            Ks[(dq + 1) * 68 + r] = kv.y;
            Ks[(dq + 2) * 68 + r] = kv.z;
            Ks[(dq + 3) * 68 + r] = kv.w;
            float4 vv = *(const float4*)(vbase + (size_t)(c0 + r) * D_ + dq);
            *(float4*)&Vs[r * 68 + dq] = vv;
        }
        __syncthreads();

        // S = (Q * scale) K^T for this 64x64 tile
        float s[4][4];
#pragma unroll
        for (int i = 0; i < 4; i++)
#pragma unroll
            for (int j = 0; j < 4; j++) s[i][j] = 0.f;

#pragma unroll 8
        for (int kk = 0; kk < 64; kk++) {
            float4 q4 = *(float4*)&Qs[kk * 68 + 4 * ty];
            float4 k4 = *(float4*)&Ks[kk * 68 + 4 * tx];
            float qa[4] = {q4.x, q4.y, q4.z, q4.w};
            float kb[4] = {k4.x, k4.y, k4.z, k4.w};
#pragma unroll
            for (int i = 0; i < 4; i++)
#pragma unroll
                for (int j = 0; j < 4; j++)
                    s[i][j] = fmaf(qa[i], kb[j], s[i][j]);
        }

        if (kt == qt) {   // causal mask on the diagonal tile
#pragma unroll
            for (int i = 0; i < 4; i++)
#pragma unroll
                for (int j = 0; j < 4; j++)
                    if (4 * tx + j > 4 * ty + i) s[i][j] = -1e30f;
        }

        // online softmax (rows 4*ty+i; reduce across the 16 tx lanes)
#pragma unroll
        for (int i = 0; i < 4; i++) {
            float mm = fmaxf(fmaxf(s[i][0], s[i][1]), fmaxf(s[i][2], s[i][3]));
#pragma unroll
            for (int off = 1; off < 16; off <<= 1)
                mm = fmaxf(mm, __shfl_xor_sync(0xffffffffu, mm, off));
            float mnew  = fmaxf(mrow[i], mm);
            float alpha = __expf(mrow[i] - mnew);
            mrow[i] = mnew;
            float ls = 0.f;
#pragma unroll
            for (int j = 0; j < 4; j++) {
                s[i][j] = __expf(s[i][j] - mnew);   // s becomes P
                ls += s[i][j];
            }
#pragma unroll
            for (int off = 1; off < 16; off <<= 1)
                ls += __shfl_xor_sync(0xffffffffu, ls, off);
            lrow[i] = lrow[i] * alpha + ls;
#pragma unroll
            for (int j = 0; j < 4; j++) accO[i][j] *= alpha;
        }

        // publish P (row-major, vectorized stores)
#pragma unroll
        for (int i = 0; i < 4; i++)
            *(float4*)&Pt[(4 * ty + i) * 68 + 4 * tx] =
                make_float4(s[i][0], s[i][1], s[i][2], s[i][3]);
        __syncthreads();

        // O += P V
#pragma unroll 4
        for (int jc = 0; jc < 64; jc += 4) {
            float4 p4[4], v4[4];
#pragma unroll
            for (int i = 0; i < 4; i++)
                p4[i] = *(float4*)&Pt[(4 * ty + i) * 68 + jc];
#pragma unroll
            for (int jj = 0; jj < 4; jj++)
                v4[jj] = *(float4*)&Vs[(jc + jj) * 68 + 4 * tx];
#pragma unroll
            for (int i = 0; i < 4; i++) {
                float p0 = p4[i].x, p1 = p4[i].y, p2 = p4[i].z, p3 = p4[i].w;
                accO[i][0] = fmaf(p0, v4[0].x, fmaf(p1, v4[1].x, fmaf(p2, v4[2].x, fmaf(p3, v4[3].x, accO[i][0]))));
                accO[i][1] = fmaf(p0, v4[0].y, fmaf(p1, v4[1].y, fmaf(p2, v4[2].y, fmaf(p3, v4[3].y, accO[i][1]))));
                accO[i][2] = fmaf(p0, v4[0].z, fmaf(p1, v4[1].z, fmaf(p2, v4[2].z, fmaf(p3, v4[3].z, accO[i][2]))));
                accO[i][3] = fmaf(p0, v4[0].w, fmaf(p1, v4[1].w, fmaf(p2, v4[2].w, fmaf(p3, v4[3].w, accO[i][3]))));
            }
        }
    }

    // normalize and write out: [B, N, F] with F index = h*64 + d
    const int bb = bh / H_;
    const int h  = bh % H_;
#pragma unroll
    for (int i = 0; i < 4; i++) {
        float inv = 1.f / lrow[i];
        int row = n0 + 4 * ty + i;
        float4 o = make_float4(accO[i][0] * inv, accO[i][1] * inv,
                               accO[i][2] * inv, accO[i][3] * inv);
        *(float4*)&out[((size_t)(bb * N_ + row)) * F_ + h * D_ + 4 * tx] = o;
    }
}

// ---------------------------------------------------------------------------
extern "C" void kernel_launch(void* const* d_in, const int* in_sizes, int n_in,
                              void* d_out, int out_size)
{
    const float* x  = (const float*)d_in[0];
    const float* Wq = (const float*)d_in[1];
    const float* bq = (const float*)d_in[2];
    const float* Wk = (const float*)d_in[3];
    const float* bk = (const float*)d_in[4];
    const float* Wv = (const float*)d_in[5];
    const float* bv = (const float*)d_in[6];
    float* out = (float*)d_out;
    (void)in_sizes; (void)n_in; (void)out_size;

    float *pq = nullptr, *pk = nullptr, *pv = nullptr;
    cudaGetSymbolAddress((void**)&pq, g_q);
    cudaGetSymbolAddress((void**)&pk, g_k);
    cudaGetSymbolAddress((void**)&pv, g_v);

    dim3 gg(F_ / 128, M_ / 128);   // (8, 64)
    qkv_gemm_kernel<<<gg, 256>>>(x, Wq, bq, pq);
    qkv_gemm_kernel<<<gg, 256>>>(x, Wk, bk, pk);
    qkv_gemm_kernel<<<gg, 256>>>(x, Wv, bv, pv);

    const int smem = 4 * 64 * 68 * (int)sizeof(float);   // 69632 B
    cudaFuncSetAttribute(flash_attn_kernel,
                         cudaFuncAttributeMaxDynamicSharedMemorySize, smem);
    dim3 ga(N_ / 64, B_ * H_);     // (32, 64)
    flash_attn_kernel<<<ga, 256, smem>>>(pq, pk, pv, out);
}

// round 3
// speedup vs baseline: 1.6495x; 1.6495x over previous
#include <cuda_runtime.h>
#include <math.h>
#include <stdint.h>

#define B_ 4
#define N_ 2048
#define F_ 1024
#define H_ 16
#define D_ 64
#define M_ (B_*N_)   // 8192 rows

// Scratch for Q/K/V in [b, h, n, d] layout (device globals = sanctioned scratch)
__device__ float g_q[(size_t)B_*H_*N_*D_];
__device__ float g_k[(size_t)B_*H_*N_*D_];
__device__ float g_v[(size_t)B_*H_*N_*D_];

__device__ __forceinline__ uint32_t f2tf32(float x) {
    uint32_t y;
    asm("cvt.rna.tf32.f32 %0, %1;" : "=r"(y) : "f"(x));
    return y;
}

__device__ __forceinline__ void mma_tf32(float& d0, float& d1, float& d2, float& d3,
                                         uint32_t a0, uint32_t a1, uint32_t a2, uint32_t a3,
                                         uint32_t b0, uint32_t b1)
{
    asm volatile("mma.sync.aligned.m16n8k8.row.col.f32.tf32.tf32.f32 "
                 "{%0,%1,%2,%3}, {%4,%5,%6,%7}, {%8,%9}, {%0,%1,%2,%3};"
                 : "+f"(d0), "+f"(d1), "+f"(d2), "+f"(d3)
                 : "r"(a0), "r"(a1), "r"(a2), "r"(a3), "r"(b0), "r"(b1));
}

// ---------------------------------------------------------------------------
// tf32 tensor-core GEMM: out[b,h,n,d] = X[m,k] @ W[k,j] + bias[j]
// 128x128 CTA tile, BK=16, 256 threads = 8 warps (2 M x 4 N), warp tile 64x32.
// Double-buffered smem, register prefetch. W consumed in native [K,N] layout.
// ---------------------------------------------------------------------------
#define BK 16
#define AS_STR 20    // pad: banks (20*m + c) % 32 conflict-free for fragment gathers
#define BS_STR 136   // pad: banks (136*k + n) % 32 conflict-free

__global__ __launch_bounds__(256, 2)
void qkv_mma_gemm(const float* __restrict__ X,
                  const float* __restrict__ W0, const float* __restrict__ W1,
                  const float* __restrict__ W2,
                  const float* __restrict__ bi0, const float* __restrict__ bi1,
                  const float* __restrict__ bi2,
                  float* __restrict__ o0, float* __restrict__ o1,
                  float* __restrict__ o2)
{
    __shared__ float As[2][128 * AS_STR];  // [m][k] m-major
    __shared__ float Bs[2][BK * BS_STR];   // [k][n] k-major (W native)

    const int z = blockIdx.z;
    const float* W    = (z == 0) ? W0 : (z == 1) ? W1 : W2;
    const float* bias = (z == 0) ? bi0 : (z == 1) ? bi1 : bi2;
    float* outp       = (z == 0) ? o0 : (z == 1) ? o1 : o2;

    const int tid  = threadIdx.x;
    const int lane = tid & 31;
    const int wid  = tid >> 5;
    const int wr   = wid & 1;          // warp M row (0..1)
    const int wc   = wid >> 1;         // warp N col (0..3)
    const int m0   = blockIdx.y * 128;
    const int n0   = blockIdx.x * 128;
    const int tg   = lane & 3;         // thread-in-group
    const int gp   = lane >> 2;        // group id (0..7)

    // global prefetch mapping (2 float4 each for A and B per tile)
    const int ar0 = tid >> 1;                 // A rows handled: tid/2, +128
    const int aq  = (tid & 1) * 2;            // but simpler: use idx scheme below

    float4 pa[2], pb[2];
    // A tile: 512 float4 (128 rows x 4 quads); idx = tid, tid+256
    // B tile: 512 float4 (16 rows x 32 quads)
    const int a_row0 = tid >> 2,  a_q0 = tid & 3;
    const int a_row1 = (tid + 256) >> 2, a_q1 = (tid + 256) & 3;
    const int b_row0 = tid >> 5,  b_q0 = tid & 31;
    const int b_row1 = (tid + 256) >> 5, b_q1 = (tid + 256) & 31;
    (void)ar0; (void)aq;

    float c[4][4][4];
#pragma unroll
    for (int i = 0; i < 4; i++)
#pragma unroll
        for (int j = 0; j < 4; j++)
#pragma unroll
            for (int r = 0; r < 4; r++) c[i][j][r] = 0.f;

    // load first tile (kt = 0)
    pa[0] = *(const float4*)&X[(size_t)(m0 + a_row0) * F_ + a_q0 * 4];
    pa[1] = *(const float4*)&X[(size_t)(m0 + a_row1) * F_ + a_q1 * 4];
    pb[0] = *(const float4*)&W[(size_t)b_row0 * F_ + n0 + b_q0 * 4];
    pb[1] = *(const float4*)&W[(size_t)b_row1 * F_ + n0 + b_q1 * 4];

    int buf = 0;
    {   // store tile 0
        float* A = As[0]; float* Bsm = Bs[0];
        *(uint32_t*)&A[a_row0 * AS_STR + a_q0 * 4 + 0] = f2tf32(pa[0].x);
        *(uint32_t*)&A[a_row0 * AS_STR + a_q0 * 4 + 1] = f2tf32(pa[0].y);
        *(uint32_t*)&A[a_row0 * AS_STR + a_q0 * 4 + 2] = f2tf32(pa[0].z);
        *(uint32_t*)&A[a_row0 * AS_STR + a_q0 * 4 + 3] = f2tf32(pa[0].w);
        *(uint32_t*)&A[a_row1 * AS_STR + a_q1 * 4 + 0] = f2tf32(pa[1].x);
        *(uint32_t*)&A[a_row1 * AS_STR + a_q1 * 4 + 1] = f2tf32(pa[1].y);
        *(uint32_t*)&A[a_row1 * AS_STR + a_q1 * 4 + 2] = f2tf32(pa[1].z);
        *(uint32_t*)&A[a_row1 * AS_STR + a_q1 * 4 + 3] = f2tf32(pa[1].w);
        *(uint32_t*)&Bsm[b_row0 * BS_STR + b_q0 * 4 + 0] = f2tf32(pb[0].x);
        *(uint32_t*)&Bsm[b_row0 * BS_STR + b_q0 * 4 + 1] = f2tf32(pb[0].y);
        *(uint32_t*)&Bsm[b_row0 * BS_STR + b_q0 * 4 + 2] = f2tf32(pb[0].z);
        *(uint32_t*)&Bsm[b_row0 * BS_STR + b_q0 * 4 + 3] = f2tf32(pb[0].w);
        *(uint32_t*)&Bsm[b_row1 * BS_STR + b_q1 * 4 + 0] = f2tf32(pb[1].x);
        *(uint32_t*)&Bsm[b_row1 * BS_STR + b_q1 * 4 + 1] = f2tf32(pb[1].y);
        *(uint32_t*)&Bsm[b_row1 * BS_STR + b_q1 * 4 + 2] = f2tf32(pb[1].z);
        *(uint32_t*)&Bsm[b_row1 * BS_STR + b_q1 * 4 + 3] = f2tf32(pb[1].w);
    }
    __syncthreads();

    const int NT = F_ / BK;   // 64
    for (int kt = 0; kt < NT; kt++) {
        // prefetch next tile into registers
        if (kt + 1 < NT) {
            const int kb = (kt + 1) * BK;
            pa[0] = *(const float4*)&X[(size_t)(m0 + a_row0) * F_ + kb + a_q0 * 4];
            pa[1] = *(const float4*)&X[(size_t)(m0 + a_row1) * F_ + kb + a_q1 * 4];
            pb[0] = *(const float4*)&W[(size_t)(kb + b_row0) * F_ + n0 + b_q0 * 4];
            pb[1] = *(const float4*)&W[(size_t)(kb + b_row1) * F_ + n0 + b_q1 * 4];
        }

        const uint32_t* A = (const uint32_t*)As[buf];
        const uint32_t* Bm = (const uint32_t*)Bs[buf];
#pragma unroll
        for (int kk = 0; kk < BK; kk += 8) {
            uint32_t af[4][4], bf[4][2];
#pragma unroll
            for (int mt = 0; mt < 4; mt++) {
                const int r = wr * 64 + mt * 16 + gp;
                af[mt][0] = A[(r    ) * AS_STR + kk + tg    ];
                af[mt][1] = A[(r + 8) * AS_STR + kk + tg    ];
                af[mt][2] = A[(r    ) * AS_STR + kk + tg + 4];
                af[mt][3] = A[(r + 8) * AS_STR + kk + tg + 4];
            }
#pragma unroll
            for (int nt = 0; nt < 4; nt++) {
                const int col = wc * 32 + nt * 8 + gp;
                bf[nt][0] = Bm[(kk + tg    ) * BS_STR + col];
                bf[nt][1] = Bm[(kk + tg + 4) * BS_STR + col];
            }
#pragma unroll
            for (int mt = 0; mt < 4; mt++)
#pragma unroll
                for (int nt = 0; nt < 4; nt++)
                    mma_tf32(c[mt][nt][0], c[mt][nt][1], c[mt][nt][2], c[mt][nt][3],
                             af[mt][0], af[mt][1], af[mt][2], af[mt][3],
                             bf[nt][0], bf[nt][1]);
        }
        __syncthreads();

        if (kt + 1 < NT) {
            float* An = As[buf ^ 1]; float* Bn = Bs[buf ^ 1];
            *(uint32_t*)&An[a_row0 * AS_STR + a_q0 * 4 + 0] = f2tf32(pa[0].x);
            *(uint32_t*)&An[a_row0 * AS_STR + a_q0 * 4 + 1] = f2tf32(pa[0].y);
            *(uint32_t*)&An[a_row0 * AS_STR + a_q0 * 4 + 2] = f2tf32(pa[0].z);
            *(uint32_t*)&An[a_row0 * AS_STR + a_q0 * 4 + 3] = f2tf32(pa[0].w);
            *(uint32_t*)&An[a_row1 * AS_STR + a_q1 * 4 + 0] = f2tf32(pa[1].x);
            *(uint32_t*)&An[a_row1 * AS_STR + a_q1 * 4 + 1] = f2tf32(pa[1].y);
            *(uint32_t*)&An[a_row1 * AS_STR + a_q1 * 4 + 2] = f2tf32(pa[1].z);
            *(uint32_t*)&An[a_row1 * AS_STR + a_q1 * 4 + 3] = f2tf32(pa[1].w);
            *(uint32_t*)&Bn[b_row0 * BS_STR + b_q0 * 4 + 0] = f2tf32(pb[0].x);
            *(uint32_t*)&Bn[b_row0 * BS_STR + b_q0 * 4 + 1] = f2tf32(pb[0].y);
            *(uint32_t*)&Bn[b_row0 * BS_STR + b_q0 * 4 + 2] = f2tf32(pb[0].z);
            *(uint32_t*)&Bn[b_row0 * BS_STR + b_q0 * 4 + 3] = f2tf32(pb[0].w);
            *(uint32_t*)&Bn[b_row1 * BS_STR + b_q1 * 4 + 0] = f2tf32(pb[1].x);
            *(uint32_t*)&Bn[b_row1 * BS_STR + b_q1 * 4 + 1] = f2tf32(pb[1].y);
            *(uint32_t*)&Bn[b_row1 * BS_STR + b_q1 * 4 + 2] = f2tf32(pb[1].z);
            *(uint32_t*)&Bn[b_row1 * BS_STR + b_q1 * 4 + 3] = f2tf32(pb[1].w);
            __syncthreads();
            buf ^= 1;
        }
    }

    // epilogue: C fragments -> out[b,h,n,d] with bias. c0,c1 are adjacent cols.
#pragma unroll
    for (int mt = 0; mt < 4; mt++) {
#pragma unroll
        for (int nt = 0; nt < 4; nt++) {
            const int j  = n0 + wc * 32 + nt * 8 + tg * 2;
            const int h  = j >> 6, dd = j & 63;
            const float bj0 = bias[j], bj1 = bias[j + 1];
            const int m  = m0 + wr * 64 + mt * 16 + gp;
            const int bb = m >> 11, nn = m & 2047;
            float2 v0 = make_float2(c[mt][nt][0] + bj0, c[mt][nt][1] + bj1);
            float2 v1 = make_float2(c[mt][nt][2] + bj0, c[mt][nt][3] + bj1);
            float* base = outp + (((size_t)(bb * H_ + h)) * N_ + nn) * D_ + dd;
            *(float2*)base = v0;
            *(float2*)(base + 8 * (size_t)D_) = v1;   // row m+8
        }
    }
}

// ---------------------------------------------------------------------------
// Causal flash attention, fp32 (unchanged, passing, rel_err 1e-6)
// ---------------------------------------------------------------------------
__global__ __launch_bounds__(256, 2)
void flash_attn_kernel(const float* __restrict__ gq,
                       const float* __restrict__ gk,
                       const float* __restrict__ gv,
                       float* __restrict__ out)
{
    extern __shared__ float sm[];
    float* Qs = sm;
    float* Ks = Qs + 64 * 68;
    float* Vs = Ks + 64 * 68;
    float* Pt = Vs + 64 * 68;

    const int tid = threadIdx.x;
    const int ty  = tid >> 4;
    const int tx  = tid & 15;
    const int qt  = blockIdx.x;
    const int bh  = blockIdx.y;
    const int n0  = qt * 64;

    const float* qbase = gq + (size_t)bh * N_ * D_;
    const float* kbase = gk + (size_t)bh * N_ * D_;
    const float* vbase = gv + (size_t)bh * N_ * D_;

    for (int c = tid; c < 64 * 16; c += 256) {
        int r  = c >> 4;
        int dq = (c & 15) << 2;
        float4 v = *(const float4*)(qbase + (size_t)(n0 + r) * D_ + dq);
        Qs[(dq + 0) * 68 + r] = v.x * 0.125f;
        Qs[(dq + 1) * 68 + r] = v.y * 0.125f;
        Qs[(dq + 2) * 68 + r] = v.z * 0.125f;
        Qs[(dq + 3) * 68 + r] = v.w * 0.125f;
    }

    float accO[4][4];
    float mrow[4], lrow[4];
#pragma unroll
    for (int i = 0; i < 4; i++) {
        mrow[i] = -1e30f;
        lrow[i] = 0.f;
#pragma unroll
        for (int j = 0; j < 4; j++) accO[i][j] = 0.f;
    }

    for (int kt = 0; kt <= qt; kt++) {
        const int c0 = kt * 64;
        __syncthreads();
        for (int c = tid; c < 64 * 16; c += 256) {
            int r  = c >> 4;
            int dq = (c & 15) << 2;
            float4 kv = *(const float4*)(kbase + (size_t)(c0 + r) * D_ + dq);
            Ks[(dq + 0) * 68 + r] = kv.x;
            Ks[(dq + 1) * 68 + r] = kv.y;
            Ks[(dq + 2) * 68 + r] = kv.z;
            Ks[(dq + 3) * 68 + r] = kv.w;
            float4 vv = *(const float4*)(vbase + (size_t)(c0 + r) * D_ + dq);
            *(float4*)&Vs[r * 68 + dq] = vv;
        }
        __syncthreads();

        float s[4][4];
#pragma unroll
        for (int i = 0; i < 4; i++)
#pragma unroll
            for (int j = 0; j < 4; j++) s[i][j] = 0.f;

#pragma unroll 8
        for (int kk = 0; kk < 64; kk++) {
            float4 q4 = *(float4*)&Qs[kk * 68 + 4 * ty];
            float4 k4 = *(float4*)&Ks[kk * 68 + 4 * tx];
            float qa[4] = {q4.x, q4.y, q4.z, q4.w};
            float kb[4] = {k4.x, k4.y, k4.z, k4.w};
#pragma unroll
            for (int i = 0; i < 4; i++)
#pragma unroll
                for (int j = 0; j < 4; j++)
                    s[i][j] = fmaf(qa[i], kb[j], s[i][j]);
        }

        if (kt == qt) {
#pragma unroll
            for (int i = 0; i < 4; i++)
#pragma unroll
                for (int j = 0; j < 4; j++)
                    if (4 * tx + j > 4 * ty + i) s[i][j] = -1e30f;
        }

#pragma unroll
        for (int i = 0; i < 4; i++) {
            float mm = fmaxf(fmaxf(s[i][0], s[i][1]), fmaxf(s[i][2], s[i][3]));
#pragma unroll
            for (int off = 1; off < 16; off <<= 1)
                mm = fmaxf(mm, __shfl_xor_sync(0xffffffffu, mm, off));
            float mnew  = fmaxf(mrow[i], mm);
            float alpha = __expf(mrow[i] - mnew);
            mrow[i] = mnew;
            float ls = 0.f;
#pragma unroll
            for (int j = 0; j < 4; j++) {
                s[i][j] = __expf(s[i][j] - mnew);
                ls += s[i][j];
            }
#pragma unroll
            for (int off = 1; off < 16; off <<= 1)
                ls += __shfl_xor_sync(0xffffffffu, ls, off);
            lrow[i] = lrow[i] * alpha + ls;
#pragma unroll
            for (int j = 0; j < 4; j++) accO[i][j] *= alpha;
        }

#pragma unroll
        for (int i = 0; i < 4; i++)
            *(float4*)&Pt[(4 * ty + i) * 68 + 4 * tx] =
                make_float4(s[i][0], s[i][1], s[i][2], s[i][3]);
        __syncthreads();

#pragma unroll 4
        for (int jc = 0; jc < 64; jc += 4) {
            float4 p4[4], v4[4];
#pragma unroll
            for (int i = 0; i < 4; i++)
                p4[i] = *(float4*)&Pt[(4 * ty + i) * 68 + jc];
#pragma unroll
            for (int jj = 0; jj < 4; jj++)
                v4[jj] = *(float4*)&Vs[(jc + jj) * 68 + 4 * tx];
#pragma unroll
            for (int i = 0; i < 4; i++) {
                float p0 = p4[i].x, p1 = p4[i].y, p2 = p4[i].z, p3 = p4[i].w;
                accO[i][0] = fmaf(p0, v4[0].x, fmaf(p1, v4[1].x, fmaf(p2, v4[2].x, fmaf(p3, v4[3].x, accO[i][0]))));
                accO[i][1] = fmaf(p0, v4[0].y, fmaf(p1, v4[1].y, fmaf(p2, v4[2].y, fmaf(p3, v4[3].y, accO[i][1]))));
                accO[i][2] = fmaf(p0, v4[0].z, fmaf(p1, v4[1].z, fmaf(p2, v4[2].z, fmaf(p3, v4[3].z, accO[i][2]))));
                accO[i][3] = fmaf(p0, v4[0].w, fmaf(p1, v4[1].w, fmaf(p2, v4[2].w, fmaf(p3, v4[3].w, accO[i][3]))));
            }
        }
    }

    const int bb = bh / H_;
    const int h  = bh % H_;
#pragma unroll
    for (int i = 0; i < 4; i++) {
        float inv = 1.f / lrow[i];
        int row = n0 + 4 * ty + i;
        float4 o = make_float4(accO[i][0] * inv, accO[i][1] * inv,
                               accO[i][2] * inv, accO[i][3] * inv);
        *(float4*)&out[((size_t)(bb * N_ + row)) * F_ + h * D_ + 4 * tx] = o;
    }
}

// ---------------------------------------------------------------------------
extern "C" void kernel_launch(void* const* d_in, const int* in_sizes, int n_in,
                              void* d_out, int out_size)
{
    const float* x  = (const float*)d_in[0];
    const float* Wq = (const float*)d_in[1];
    const float* bq = (const float*)d_in[2];
    const float* Wk = (const float*)d_in[3];
    const float* bk = (const float*)d_in[4];
    const float* Wv = (const float*)d_in[5];
    const float* bv = (const float*)d_in[6];
    float* out = (float*)d_out;
    (void)in_sizes; (void)n_in; (void)out_size;

    float *pq = nullptr, *pk = nullptr, *pv = nullptr;
    cudaGetSymbolAddress((void**)&pq, g_q);
    cudaGetSymbolAddress((void**)&pk, g_k);
    cudaGetSymbolAddress((void**)&pv, g_v);

    // tf32 tensor-core QKV projections (z selects Q/K/V)
    qkv_mma_gemm<<<dim3(F_ / 128, M_ / 128, 3), 256>>>(
        x, Wq, Wk, Wv, bq, bk, bv, pq, pk, pv);

    // causal flash attention (fp32)
    const int smem = 4 * 64 * 68 * (int)sizeof(float);
    cudaFuncSetAttribute(flash_attn_kernel,
                         cudaFuncAttributeMaxDynamicSharedMemorySize, smem);
    flash_attn_kernel<<<dim3(N_ / 64, B_ * H_), 256, smem>>>(pq, pk, pv, out);
}

// round 4
// speedup vs baseline: 3.0507x; 1.8494x over previous
#include <cuda_runtime.h>
#include <math.h>
#include <stdint.h>

#define B_ 4
#define N_ 2048
#define F_ 1024
#define H_ 16
#define D_ 64
#define M_ (B_*N_)   // 8192 rows

// Scratch for Q/K/V in [b, h, n, d] layout
__device__ float g_q[(size_t)B_*H_*N_*D_];
__device__ float g_k[(size_t)B_*H_*N_*D_];
__device__ float g_v[(size_t)B_*H_*N_*D_];

__device__ __forceinline__ uint32_t f2tf32(float x) {
    uint32_t y;
    asm("cvt.rna.tf32.f32 %0, %1;" : "=r"(y) : "f"(x));
    return y;
}
__device__ __forceinline__ float ex2f(float x) {
    float y;
    asm("ex2.approx.ftz.f32 %0, %1;" : "=f"(y) : "f"(x));
    return y;
}
__device__ __forceinline__ void mma_tf32(float& d0, float& d1, float& d2, float& d3,
                                         uint32_t a0, uint32_t a1, uint32_t a2, uint32_t a3,
                                         uint32_t b0, uint32_t b1)
{
    asm volatile("mma.sync.aligned.m16n8k8.row.col.f32.tf32.tf32.f32 "
                 "{%0,%1,%2,%3}, {%4,%5,%6,%7}, {%8,%9}, {%0,%1,%2,%3};"
                 : "+f"(d0), "+f"(d1), "+f"(d2), "+f"(d3)
                 : "r"(a0), "r"(a1), "r"(a2), "r"(a3), "r"(b0), "r"(b1));
}

// ---------------------------------------------------------------------------
// tf32 tensor-core GEMM (unchanged from round 3, passing)
// ---------------------------------------------------------------------------
#define BK 16
#define AS_STR 20
#define BS_STR 136

__global__ __launch_bounds__(256, 2)
void qkv_mma_gemm(const float* __restrict__ X,
                  const float* __restrict__ W0, const float* __restrict__ W1,
                  const float* __restrict__ W2,
                  const float* __restrict__ bi0, const float* __restrict__ bi1,
                  const float* __restrict__ bi2,
                  float* __restrict__ o0, float* __restrict__ o1,
                  float* __restrict__ o2)
{
    __shared__ float As[2][128 * AS_STR];
    __shared__ float Bs[2][BK * BS_STR];

    const int z = blockIdx.z;
    const float* W    = (z == 0) ? W0 : (z == 1) ? W1 : W2;
    const float* bias = (z == 0) ? bi0 : (z == 1) ? bi1 : bi2;
    float* outp       = (z == 0) ? o0 : (z == 1) ? o1 : o2;

    const int tid  = threadIdx.x;
    const int lane = tid & 31;
    const int wid  = tid >> 5;
    const int wr   = wid & 1;
    const int wc   = wid >> 1;
    const int m0   = blockIdx.y * 128;
    const int n0   = blockIdx.x * 128;
    const int tg   = lane & 3;
    const int gp   = lane >> 2;

    float4 pa[2], pb[2];
    const int a_row0 = tid >> 2,  a_q0 = tid & 3;
    const int a_row1 = (tid + 256) >> 2, a_q1 = (tid + 256) & 3;
    const int b_row0 = tid >> 5,  b_q0 = tid & 31;
    const int b_row1 = (tid + 256) >> 5, b_q1 = (tid + 256) & 31;

    float c[4][4][4];
#pragma unroll
    for (int i = 0; i < 4; i++)
#pragma unroll
        for (int j = 0; j < 4; j++)
#pragma unroll
            for (int r = 0; r < 4; r++) c[i][j][r] = 0.f;

    pa[0] = *(const float4*)&X[(size_t)(m0 + a_row0) * F_ + a_q0 * 4];
    pa[1] = *(const float4*)&X[(size_t)(m0 + a_row1) * F_ + a_q1 * 4];
    pb[0] = *(const float4*)&W[(size_t)b_row0 * F_ + n0 + b_q0 * 4];
    pb[1] = *(const float4*)&W[(size_t)b_row1 * F_ + n0 + b_q1 * 4];

    int buf = 0;
    {
        float* A = As[0]; float* Bsm = Bs[0];
        *(uint32_t*)&A[a_row0 * AS_STR + a_q0 * 4 + 0] = f2tf32(pa[0].x);
        *(uint32_t*)&A[a_row0 * AS_STR + a_q0 * 4 + 1] = f2tf32(pa[0].y);
        *(uint32_t*)&A[a_row0 * AS_STR + a_q0 * 4 + 2] = f2tf32(pa[0].z);
        *(uint32_t*)&A[a_row0 * AS_STR + a_q0 * 4 + 3] = f2tf32(pa[0].w);
        *(uint32_t*)&A[a_row1 * AS_STR + a_q1 * 4 + 0] = f2tf32(pa[1].x);
        *(uint32_t*)&A[a_row1 * AS_STR + a_q1 * 4 + 1] = f2tf32(pa[1].y);
        *(uint32_t*)&A[a_row1 * AS_STR + a_q1 * 4 + 2] = f2tf32(pa[1].z);
        *(uint32_t*)&A[a_row1 * AS_STR + a_q1 * 4 + 3] = f2tf32(pa[1].w);
        *(uint32_t*)&Bsm[b_row0 * BS_STR + b_q0 * 4 + 0] = f2tf32(pb[0].x);
        *(uint32_t*)&Bsm[b_row0 * BS_STR + b_q0 * 4 + 1] = f2tf32(pb[0].y);
        *(uint32_t*)&Bsm[b_row0 * BS_STR + b_q0 * 4 + 2] = f2tf32(pb[0].z);
        *(uint32_t*)&Bsm[b_row0 * BS_STR + b_q0 * 4 + 3] = f2tf32(pb[0].w);
        *(uint32_t*)&Bsm[b_row1 * BS_STR + b_q1 * 4 + 0] = f2tf32(pb[1].x);
        *(uint32_t*)&Bsm[b_row1 * BS_STR + b_q1 * 4 + 1] = f2tf32(pb[1].y);
        *(uint32_t*)&Bsm[b_row1 * BS_STR + b_q1 * 4 + 2] = f2tf32(pb[1].z);
        *(uint32_t*)&Bsm[b_row1 * BS_STR + b_q1 * 4 + 3] = f2tf32(pb[1].w);
    }
    __syncthreads();

    const int NT = F_ / BK;
    for (int kt = 0; kt < NT; kt++) {
        if (kt + 1 < NT) {
            const int kb = (kt + 1) * BK;
            pa[0] = *(const float4*)&X[(size_t)(m0 + a_row0) * F_ + kb + a_q0 * 4];
            pa[1] = *(const float4*)&X[(size_t)(m0 + a_row1) * F_ + kb + a_q1 * 4];
            pb[0] = *(const float4*)&W[(size_t)(kb + b_row0) * F_ + n0 + b_q0 * 4];
            pb[1] = *(const float4*)&W[(size_t)(kb + b_row1) * F_ + n0 + b_q1 * 4];
        }

        const uint32_t* A = (const uint32_t*)As[buf];
        const uint32_t* Bm = (const uint32_t*)Bs[buf];
#pragma unroll
        for (int kk = 0; kk < BK; kk += 8) {
            uint32_t af[4][4], bf[4][2];
#pragma unroll
            for (int mt = 0; mt < 4; mt++) {
                const int r = wr * 64 + mt * 16 + gp;
                af[mt][0] = A[(r    ) * AS_STR + kk + tg    ];
                af[mt][1] = A[(r + 8) * AS_STR + kk + tg    ];
                af[mt][2] = A[(r    ) * AS_STR + kk + tg + 4];
                af[mt][3] = A[(r + 8) * AS_STR + kk + tg + 4];
            }
#pragma unroll
            for (int nt = 0; nt < 4; nt++) {
                const int col = wc * 32 + nt * 8 + gp;
                bf[nt][0] = Bm[(kk + tg    ) * BS_STR + col];
                bf[nt][1] = Bm[(kk + tg + 4) * BS_STR + col];
            }
#pragma unroll
            for (int mt = 0; mt < 4; mt++)
#pragma unroll
                for (int nt = 0; nt < 4; nt++)
                    mma_tf32(c[mt][nt][0], c[mt][nt][1], c[mt][nt][2], c[mt][nt][3],
                             af[mt][0], af[mt][1], af[mt][2], af[mt][3],
                             bf[nt][0], bf[nt][1]);
        }
        __syncthreads();

        if (kt + 1 < NT) {
            float* An = As[buf ^ 1]; float* Bn = Bs[buf ^ 1];
            *(uint32_t*)&An[a_row0 * AS_STR + a_q0 * 4 + 0] = f2tf32(pa[0].x);
            *(uint32_t*)&An[a_row0 * AS_STR + a_q0 * 4 + 1] = f2tf32(pa[0].y);
            *(uint32_t*)&An[a_row0 * AS_STR + a_q0 * 4 + 2] = f2tf32(pa[0].z);
            *(uint32_t*)&An[a_row0 * AS_STR + a_q0 * 4 + 3] = f2tf32(pa[0].w);
            *(uint32_t*)&An[a_row1 * AS_STR + a_q1 * 4 + 0] = f2tf32(pa[1].x);
            *(uint32_t*)&An[a_row1 * AS_STR + a_q1 * 4 + 1] = f2tf32(pa[1].y);
            *(uint32_t*)&An[a_row1 * AS_STR + a_q1 * 4 + 2] = f2tf32(pa[1].z);
            *(uint32_t*)&An[a_row1 * AS_STR + a_q1 * 4 + 3] = f2tf32(pa[1].w);
            *(uint32_t*)&Bn[b_row0 * BS_STR + b_q0 * 4 + 0] = f2tf32(pb[0].x);
            *(uint32_t*)&Bn[b_row0 * BS_STR + b_q0 * 4 + 1] = f2tf32(pb[0].y);
            *(uint32_t*)&Bn[b_row0 * BS_STR + b_q0 * 4 + 2] = f2tf32(pb[0].z);
            *(uint32_t*)&Bn[b_row0 * BS_STR + b_q0 * 4 + 3] = f2tf32(pb[0].w);
            *(uint32_t*)&Bn[b_row1 * BS_STR + b_q1 * 4 + 0] = f2tf32(pb[1].x);
            *(uint32_t*)&Bn[b_row1 * BS_STR + b_q1 * 4 + 1] = f2tf32(pb[1].y);
            *(uint32_t*)&Bn[b_row1 * BS_STR + b_q1 * 4 + 2] = f2tf32(pb[1].z);
            *(uint32_t*)&Bn[b_row1 * BS_STR + b_q1 * 4 + 3] = f2tf32(pb[1].w);
            __syncthreads();
            buf ^= 1;
        }
    }

#pragma unroll
    for (int mt = 0; mt < 4; mt++) {
#pragma unroll
        for (int nt = 0; nt < 4; nt++) {
            const int j  = n0 + wc * 32 + nt * 8 + tg * 2;
            const int h  = j >> 6, dd = j & 63;
            const float bj0 = bias[j], bj1 = bias[j + 1];
            const int m  = m0 + wr * 64 + mt * 16 + gp;
            const int bb = m >> 11, nn = m & 2047;
            float2 v0 = make_float2(c[mt][nt][0] + bj0, c[mt][nt][1] + bj1);
            float2 v1 = make_float2(c[mt][nt][2] + bj0, c[mt][nt][3] + bj1);
            float* base = outp + (((size_t)(bb * H_ + h)) * N_ + nn) * D_ + dd;
            *(float2*)base = v0;
            *(float2*)(base + 8 * (size_t)D_) = v1;
        }
    }
}

// ---------------------------------------------------------------------------
// tf32 tensor-core causal flash attention.
// CTA: 128 Q rows x one (b,h). 8 warps, warp = 16 rows x 64 KV cols.
// Q fragments in registers; K/V double-buffered smem; P via smem (Q buffer).
// ---------------------------------------------------------------------------
#define PS_STR 68
#define KS_STR 68
#define VS_STR 72
#define FLASH_SMEM ((128*PS_STR + 2*64*KS_STR + 2*64*VS_STR) * 4)  // 106496 B

__global__ __launch_bounds__(256)
void flash_mma(const float* __restrict__ gq, const float* __restrict__ gk,
               const float* __restrict__ gv, float* __restrict__ out)
{
    extern __shared__ __align__(16) uint32_t smu[];
    uint32_t* Ps = smu;                      // 128x68: Q (tf32) then P
    uint32_t* Ks = Ps + 128 * PS_STR;        // 2 x 64x68
    uint32_t* Vs = Ks + 2 * 64 * KS_STR;     // 2 x 64x72

    const int tid = threadIdx.x, lane = tid & 31, wid = tid >> 5;
    const int gp = lane >> 2, tg = lane & 3;
    const int qt = (int)gridDim.x - 1 - (int)blockIdx.x;  // heavy tiles first
    const int bh = blockIdx.y;
    const int n0 = qt * 128;
    const int nkt = 2 * qt + 2;

    const float* qb = gq + (size_t)bh * (N_ * D_);
    const float* kb = gk + (size_t)bh * (N_ * D_);
    const float* vb = gv + (size_t)bh * (N_ * D_);

    const float QSC = 0.125f * 1.4426950408889634f;  // scale * log2(e)

    // Q -> smem (prescaled, tf32)
    for (int idx = tid; idx < 128 * 16; idx += 256) {
        int r = idx >> 4, q = (idx & 15) * 4;
        float4 v = *(const float4*)(qb + (size_t)(n0 + r) * D_ + q);
        *(uint4*)(Ps + r * PS_STR + q) =
            make_uint4(f2tf32(v.x * QSC), f2tf32(v.y * QSC),
                       f2tf32(v.z * QSC), f2tf32(v.w * QSC));
    }
    __syncthreads();

    const int r0 = wid * 16 + gp;
    uint32_t qf[8][4];
#pragma unroll
    for (int ks = 0; ks < 8; ks++) {
        int k0 = ks * 8;
        qf[ks][0] = Ps[r0 * PS_STR + k0 + tg];
        qf[ks][1] = Ps[(r0 + 8) * PS_STR + k0 + tg];
        qf[ks][2] = Ps[r0 * PS_STR + k0 + tg + 4];
        qf[ks][3] = Ps[(r0 + 8) * PS_STR + k0 + tg + 4];
    }
    __syncthreads();

    // KV loader mapping: 4 threads per row, 4 float4 each
    const int kr = tid >> 2, kc = (tid & 3) * 16;

    float4 kreg[4], vreg[4];
    {   // prologue: tile 0
        const float* kp = kb + (size_t)kr * D_ + kc;
        const float* vp = vb + (size_t)kr * D_ + kc;
#pragma unroll
        for (int i = 0; i < 4; i++) {
            kreg[i] = *(const float4*)(kp + 4 * i);
            vreg[i] = *(const float4*)(vp + 4 * i);
        }
        uint32_t* kd = Ks + kr * KS_STR + kc;
        uint32_t* vd = Vs + kr * VS_STR + kc;
#pragma unroll
        for (int i = 0; i < 4; i++) {
            *(uint4*)(kd + 4 * i) = make_uint4(f2tf32(kreg[i].x), f2tf32(kreg[i].y),
                                               f2tf32(kreg[i].z), f2tf32(kreg[i].w));
            *(uint4*)(vd + 4 * i) = make_uint4(f2tf32(vreg[i].x), f2tf32(vreg[i].y),
                                               f2tf32(vreg[i].z), f2tf32(vreg[i].w));
        }
    }
    __syncthreads();

    float m0 = -1e30f, m1 = -1e30f, l0 = 0.f, l1 = 0.f;
    float o[8][4];
#pragma unroll
    for (int nt = 0; nt < 8; nt++)
#pragma unroll
        for (int e = 0; e < 4; e++) o[nt][e] = 0.f;

    int buf = 0;
    for (int kt = 0; kt < nkt; kt++) {
        const int c0 = kt * 64;

        // --- S = Q K^T (128x64 tile; this warp: rows r0, r0+8) ---
        float s[8][4];
#pragma unroll
        for (int nt = 0; nt < 8; nt++)
#pragma unroll
            for (int e = 0; e < 4; e++) s[nt][e] = 0.f;

        const uint32_t* Kb = Ks + buf * (64 * KS_STR);
#pragma unroll
        for (int ks = 0; ks < 8; ks++) {
            const int k0 = ks * 8;
            uint32_t b0[8], b1[8];
#pragma unroll
            for (int nt = 0; nt < 8; nt++) {
                const uint32_t* kp2 = Kb + (nt * 8 + gp) * KS_STR + k0 + tg;
                b0[nt] = kp2[0];
                b1[nt] = kp2[4];
            }
#pragma unroll
            for (int nt = 0; nt < 8; nt++)
                mma_tf32(s[nt][0], s[nt][1], s[nt][2], s[nt][3],
                         qf[ks][0], qf[ks][1], qf[ks][2], qf[ks][3],
                         b0[nt], b1[nt]);
        }

        // --- causal mask (only the last two tiles straddle the diagonal) ---
        if (kt >= 2 * qt) {
            const int i0g = n0 + r0, i1g = i0g + 8;
#pragma unroll
            for (int nt = 0; nt < 8; nt++) {
                const int j0 = c0 + nt * 8 + 2 * tg;
                if (j0     > i0g) s[nt][0] = -1e30f;
                if (j0 + 1 > i0g) s[nt][1] = -1e30f;
                if (j0     > i1g) s[nt][2] = -1e30f;
                if (j0 + 1 > i1g) s[nt][3] = -1e30f;
            }
        }

        // --- online softmax (log2 domain), rows r0 / r0+8 ---
        float mx0 = -1e30f, mx1 = -1e30f;
#pragma unroll
        for (int nt = 0; nt < 8; nt++) {
            mx0 = fmaxf(mx0, fmaxf(s[nt][0], s[nt][1]));
            mx1 = fmaxf(mx1, fmaxf(s[nt][2], s[nt][3]));
        }
        mx0 = fmaxf(mx0, __shfl_xor_sync(0xffffffffu, mx0, 1));
        mx0 = fmaxf(mx0, __shfl_xor_sync(0xffffffffu, mx0, 2));
        mx1 = fmaxf(mx1, __shfl_xor_sync(0xffffffffu, mx1, 1));
        mx1 = fmaxf(mx1, __shfl_xor_sync(0xffffffffu, mx1, 2));

        const float mn0 = fmaxf(m0, mx0), mn1 = fmaxf(m1, mx1);
        const float al0 = ex2f(m0 - mn0), al1 = ex2f(m1 - mn1);
        m0 = mn0; m1 = mn1;

        float ls0 = 0.f, ls1 = 0.f;
#pragma unroll
        for (int nt = 0; nt < 8; nt++) {
            s[nt][0] = ex2f(s[nt][0] - mn0);
            s[nt][1] = ex2f(s[nt][1] - mn0);
            s[nt][2] = ex2f(s[nt][2] - mn1);
            s[nt][3] = ex2f(s[nt][3] - mn1);
            ls0 += s[nt][0] + s[nt][1];
            ls1 += s[nt][2] + s[nt][3];
        }
        ls0 += __shfl_xor_sync(0xffffffffu, ls0, 1);
        ls0 += __shfl_xor_sync(0xffffffffu, ls0, 2);
        ls1 += __shfl_xor_sync(0xffffffffu, ls1, 1);
        ls1 += __shfl_xor_sync(0xffffffffu, ls1, 2);
        l0 = l0 * al0 + ls0;
        l1 = l1 * al1 + ls1;
#pragma unroll
        for (int nt = 0; nt < 8; nt++) {
            o[nt][0] *= al0; o[nt][1] *= al0;
            o[nt][2] *= al1; o[nt][3] *= al1;
        }

        // --- publish P (tf32) into the Q/P buffer (own rows only) ---
#pragma unroll
        for (int nt = 0; nt < 8; nt++) {
            *(uint2*)(Ps + r0 * PS_STR + nt * 8 + 2 * tg) =
                make_uint2(f2tf32(s[nt][0]), f2tf32(s[nt][1]));
            *(uint2*)(Ps + (r0 + 8) * PS_STR + nt * 8 + 2 * tg) =
                make_uint2(f2tf32(s[nt][2]), f2tf32(s[nt][3]));
        }
        __syncwarp();

        // --- prefetch next K/V tile into registers (latency hidden by PV) ---
        if (kt + 1 < nkt) {
            const float* kp = kb + (size_t)(c0 + 64 + kr) * D_ + kc;
            const float* vp = vb + (size_t)(c0 + 64 + kr) * D_ + kc;
#pragma unroll
            for (int i = 0; i < 4; i++) {
                kreg[i] = *(const float4*)(kp + 4 * i);
                vreg[i] = *(const float4*)(vp + 4 * i);
            }
        }

        // --- O += P V ---
        const uint32_t* Vb = Vs + buf * (64 * VS_STR);
#pragma unroll
        for (int ks = 0; ks < 8; ks++) {
            const int k0 = ks * 8;
            const uint32_t a0 = Ps[r0 * PS_STR + k0 + tg];
            const uint32_t a1 = Ps[(r0 + 8) * PS_STR + k0 + tg];
            const uint32_t a2 = Ps[r0 * PS_STR + k0 + tg + 4];
            const uint32_t a3 = Ps[(r0 + 8) * PS_STR + k0 + tg + 4];
            uint32_t b0[8], b1[8];
#pragma unroll
            for (int nt = 0; nt < 8; nt++) {
                b0[nt] = Vb[(k0 + tg) * VS_STR + nt * 8 + gp];
                b1[nt] = Vb[(k0 + tg + 4) * VS_STR + nt * 8 + gp];
            }
#pragma unroll
            for (int nt = 0; nt < 8; nt++)
                mma_tf32(o[nt][0], o[nt][1], o[nt][2], o[nt][3],
                         a0, a1, a2, a3, b0[nt], b1[nt]);
        }

        // --- stage next tile into the other buffer ---
        if (kt + 1 < nkt) {
            uint32_t* kd = Ks + (buf ^ 1) * (64 * KS_STR) + kr * KS_STR + kc;
            uint32_t* vd = Vs + (buf ^ 1) * (64 * VS_STR) + kr * VS_STR + kc;
#pragma unroll
            for (int i = 0; i < 4; i++) {
                *(uint4*)(kd + 4 * i) = make_uint4(f2tf32(kreg[i].x), f2tf32(kreg[i].y),
                                                   f2tf32(kreg[i].z), f2tf32(kreg[i].w));
                *(uint4*)(vd + 4 * i) = make_uint4(f2tf32(vreg[i].x), f2tf32(vreg[i].y),
                                                   f2tf32(vreg[i].z), f2tf32(vreg[i].w));
            }
            __syncthreads();
            buf ^= 1;
        }
    }

    // --- normalize and write out [B, N, F] ---
    const float inv0 = 1.f / l0, inv1 = 1.f / l1;
    const int bb = bh >> 4, h = bh & 15;
    float* base = out + ((size_t)(bb * N_ + n0 + r0)) * F_ + h * D_;
#pragma unroll
    for (int nt = 0; nt < 8; nt++) {
        const int d = nt * 8 + 2 * tg;
        *(float2*)(base + d) = make_float2(o[nt][0] * inv0, o[nt][1] * inv0);
        *(float2*)(base + 8 * F_ + d) = make_float2(o[nt][2] * inv1, o[nt][3] * inv1);
    }
}

// ---------------------------------------------------------------------------
extern "C" void kernel_launch(void* const* d_in, const int* in_sizes, int n_in,
                              void* d_out, int out_size)
{
    const float* x  = (const float*)d_in[0];
    const float* Wq = (const float*)d_in[1];
    const float* bq = (const float*)d_in[2];
    const float* Wk = (const float*)d_in[3];
    const float* bk = (const float*)d_in[4];
    const float* Wv = (const float*)d_in[5];
    const float* bv = (const float*)d_in[6];
    float* out = (float*)d_out;
    (void)in_sizes; (void)n_in; (void)out_size;

    float *pq = nullptr, *pk = nullptr, *pv = nullptr;
    cudaGetSymbolAddress((void**)&pq, g_q);
    cudaGetSymbolAddress((void**)&pk, g_k);
    cudaGetSymbolAddress((void**)&pv, g_v);

    qkv_mma_gemm<<<dim3(F_ / 128, M_ / 128, 3), 256>>>(
        x, Wq, Wk, Wv, bq, bk, bv, pq, pk, pv);

    cudaFuncSetAttribute(flash_mma,
                         cudaFuncAttributeMaxDynamicSharedMemorySize, FLASH_SMEM);
    flash_mma<<<dim3(N_ / 128, B_ * H_), 256, FLASH_SMEM>>>(pq, pk, pv, out);
}

// round 5
// speedup vs baseline: 3.1183x; 1.0222x over previous
#include <cuda_runtime.h>
#include <math.h>
#include <stdint.h>

#define B_ 4
#define N_ 2048
#define F_ 1024
#define H_ 16
#define D_ 64
#define M_ (B_*N_)   // 8192 rows

// Scratch for Q/K/V in [b, h, n, d] layout
__device__ float g_q[(size_t)B_*H_*N_*D_];
__device__ float g_k[(size_t)B_*H_*N_*D_];
__device__ float g_v[(size_t)B_*H_*N_*D_];

__device__ __forceinline__ uint32_t f2tf32(float x) {
    uint32_t y;
    asm("cvt.rna.tf32.f32 %0, %1;" : "=r"(y) : "f"(x));
    return y;
}
__device__ __forceinline__ float ex2f(float x) {
    float y;
    asm("ex2.approx.ftz.f32 %0, %1;" : "=f"(y) : "f"(x));
    return y;
}
__device__ __forceinline__ uint32_t smem_u32(const void* p) {
    uint32_t a;
    asm("{ .reg .u64 t; cvta.to.shared.u64 t, %1; cvt.u32.u64 %0, t; }" : "=r"(a) : "l"(p));
    return a;
}
__device__ __forceinline__ void mma_tf32(float& d0, float& d1, float& d2, float& d3,
                                         uint32_t a0, uint32_t a1, uint32_t a2, uint32_t a3,
                                         uint32_t b0, uint32_t b1)
{
    asm volatile("mma.sync.aligned.m16n8k8.row.col.f32.tf32.tf32.f32 "
                 "{%0,%1,%2,%3}, {%4,%5,%6,%7}, {%8,%9}, {%0,%1,%2,%3};"
                 : "+f"(d0), "+f"(d1), "+f"(d2), "+f"(d3)
                 : "r"(a0), "r"(a1), "r"(a2), "r"(a3), "r"(b0), "r"(b1));
}
__device__ __forceinline__ void ldsm_x4(uint32_t& r0, uint32_t& r1, uint32_t& r2, uint32_t& r3,
                                        uint32_t addr)
{
    asm volatile("ldmatrix.sync.aligned.m8n8.x4.shared.b16 {%0,%1,%2,%3}, [%4];"
                 : "=r"(r0), "=r"(r1), "=r"(r2), "=r"(r3) : "r"(addr));
}

// ---------------------------------------------------------------------------
// tf32 tensor-core GEMM (unchanged from round 3/4, passing)
// ---------------------------------------------------------------------------
#define BK 16
#define AS_STR 20
#define BS_STR 136

__global__ __launch_bounds__(256, 2)
void qkv_mma_gemm(const float* __restrict__ X,
                  const float* __restrict__ W0, const float* __restrict__ W1,
                  const float* __restrict__ W2,
                  const float* __restrict__ bi0, const float* __restrict__ bi1,
                  const float* __restrict__ bi2,
                  float* __restrict__ o0, float* __restrict__ o1,
                  float* __restrict__ o2)
{
    __shared__ float As[2][128 * AS_STR];
    __shared__ float Bs[2][BK * BS_STR];

    const int z = blockIdx.z;
    const float* W    = (z == 0) ? W0 : (z == 1) ? W1 : W2;
    const float* bias = (z == 0) ? bi0 : (z == 1) ? bi1 : bi2;
    float* outp       = (z == 0) ? o0 : (z == 1) ? o1 : o2;

    const int tid  = threadIdx.x;
    const int lane = tid & 31;
    const int wid  = tid >> 5;
    const int wr   = wid & 1;
    const int wc   = wid >> 1;
    const int m0   = blockIdx.y * 128;
    const int n0   = blockIdx.x * 128;
    const int tg   = lane & 3;
    const int gp   = lane >> 2;

    float4 pa[2], pb[2];
    const int a_row0 = tid >> 2,  a_q0 = tid & 3;
    const int a_row1 = (tid + 256) >> 2, a_q1 = (tid + 256) & 3;
    const int b_row0 = tid >> 5,  b_q0 = tid & 31;
    const int b_row1 = (tid + 256) >> 5, b_q1 = (tid + 256) & 31;

    float c[4][4][4];
#pragma unroll
    for (int i = 0; i < 4; i++)
#pragma unroll
        for (int j = 0; j < 4; j++)
#pragma unroll
            for (int r = 0; r < 4; r++) c[i][j][r] = 0.f;

    pa[0] = *(const float4*)&X[(size_t)(m0 + a_row0) * F_ + a_q0 * 4];
    pa[1] = *(const float4*)&X[(size_t)(m0 + a_row1) * F_ + a_q1 * 4];
    pb[0] = *(const float4*)&W[(size_t)b_row0 * F_ + n0 + b_q0 * 4];
    pb[1] = *(const float4*)&W[(size_t)b_row1 * F_ + n0 + b_q1 * 4];

    int buf = 0;
    {
        float* A = As[0]; float* Bsm = Bs[0];
        *(uint32_t*)&A[a_row0 * AS_STR + a_q0 * 4 + 0] = f2tf32(pa[0].x);
        *(uint32_t*)&A[a_row0 * AS_STR + a_q0 * 4 + 1] = f2tf32(pa[0].y);
        *(uint32_t*)&A[a_row0 * AS_STR + a_q0 * 4 + 2] = f2tf32(pa[0].z);
        *(uint32_t*)&A[a_row0 * AS_STR + a_q0 * 4 + 3] = f2tf32(pa[0].w);
        *(uint32_t*)&A[a_row1 * AS_STR + a_q1 * 4 + 0] = f2tf32(pa[1].x);
        *(uint32_t*)&A[a_row1 * AS_STR + a_q1 * 4 + 1] = f2tf32(pa[1].y);
        *(uint32_t*)&A[a_row1 * AS_STR + a_q1 * 4 + 2] = f2tf32(pa[1].z);
        *(uint32_t*)&A[a_row1 * AS_STR + a_q1 * 4 + 3] = f2tf32(pa[1].w);
        *(uint32_t*)&Bsm[b_row0 * BS_STR + b_q0 * 4 + 0] = f2tf32(pb[0].x);
        *(uint32_t*)&Bsm[b_row0 * BS_STR + b_q0 * 4 + 1] = f2tf32(pb[0].y);
        *(uint32_t*)&Bsm[b_row0 * BS_STR + b_q0 * 4 + 2] = f2tf32(pb[0].z);
        *(uint32_t*)&Bsm[b_row0 * BS_STR + b_q0 * 4 + 3] = f2tf32(pb[0].w);
        *(uint32_t*)&Bsm[b_row1 * BS_STR + b_q1 * 4 + 0] = f2tf32(pb[1].x);
        *(uint32_t*)&Bsm[b_row1 * BS_STR + b_q1 * 4 + 1] = f2tf32(pb[1].y);
        *(uint32_t*)&Bsm[b_row1 * BS_STR + b_q1 * 4 + 2] = f2tf32(pb[1].z);
        *(uint32_t*)&Bsm[b_row1 * BS_STR + b_q1 * 4 + 3] = f2tf32(pb[1].w);
    }
    __syncthreads();

    const int NT = F_ / BK;
    for (int kt = 0; kt < NT; kt++) {
        if (kt + 1 < NT) {
            const int kb = (kt + 1) * BK;
            pa[0] = *(const float4*)&X[(size_t)(m0 + a_row0) * F_ + kb + a_q0 * 4];
            pa[1] = *(const float4*)&X[(size_t)(m0 + a_row1) * F_ + kb + a_q1 * 4];
            pb[0] = *(const float4*)&W[(size_t)(kb + b_row0) * F_ + n0 + b_q0 * 4];
            pb[1] = *(const float4*)&W[(size_t)(kb + b_row1) * F_ + n0 + b_q1 * 4];
        }

        const uint32_t* A = (const uint32_t*)As[buf];
        const uint32_t* Bm = (const uint32_t*)Bs[buf];
#pragma unroll
        for (int kk = 0; kk < BK; kk += 8) {
            uint32_t af[4][4], bf[4][2];
#pragma unroll
            for (int mt = 0; mt < 4; mt++) {
                const int r = wr * 64 + mt * 16 + gp;
                af[mt][0] = A[(r    ) * AS_STR + kk + tg    ];
                af[mt][1] = A[(r + 8) * AS_STR + kk + tg    ];
                af[mt][2] = A[(r    ) * AS_STR + kk + tg + 4];
                af[mt][3] = A[(r + 8) * AS_STR + kk + tg + 4];
            }
#pragma unroll
            for (int nt = 0; nt < 4; nt++) {
                const int col = wc * 32 + nt * 8 + gp;
                bf[nt][0] = Bm[(kk + tg    ) * BS_STR + col];
                bf[nt][1] = Bm[(kk + tg + 4) * BS_STR + col];
            }
#pragma unroll
            for (int mt = 0; mt < 4; mt++)
#pragma unroll
                for (int nt = 0; nt < 4; nt++)
                    mma_tf32(c[mt][nt][0], c[mt][nt][1], c[mt][nt][2], c[mt][nt][3],
                             af[mt][0], af[mt][1], af[mt][2], af[mt][3],
                             bf[nt][0], bf[nt][1]);
        }
        __syncthreads();

        if (kt + 1 < NT) {
            float* An = As[buf ^ 1]; float* Bn = Bs[buf ^ 1];
            *(uint32_t*)&An[a_row0 * AS_STR + a_q0 * 4 + 0] = f2tf32(pa[0].x);
            *(uint32_t*)&An[a_row0 * AS_STR + a_q0 * 4 + 1] = f2tf32(pa[0].y);
            *(uint32_t*)&An[a_row0 * AS_STR + a_q0 * 4 + 2] = f2tf32(pa[0].z);
            *(uint32_t*)&An[a_row0 * AS_STR + a_q0 * 4 + 3] = f2tf32(pa[0].w);
            *(uint32_t*)&An[a_row1 * AS_STR + a_q1 * 4 + 0] = f2tf32(pa[1].x);
            *(uint32_t*)&An[a_row1 * AS_STR + a_q1 * 4 + 1] = f2tf32(pa[1].y);
            *(uint32_t*)&An[a_row1 * AS_STR + a_q1 * 4 + 2] = f2tf32(pa[1].z);
            *(uint32_t*)&An[a_row1 * AS_STR + a_q1 * 4 + 3] = f2tf32(pa[1].w);
            *(uint32_t*)&Bn[b_row0 * BS_STR + b_q0 * 4 + 0] = f2tf32(pb[0].x);
            *(uint32_t*)&Bn[b_row0 * BS_STR + b_q0 * 4 + 1] = f2tf32(pb[0].y);
            *(uint32_t*)&Bn[b_row0 * BS_STR + b_q0 * 4 + 2] = f2tf32(pb[0].z);
            *(uint32_t*)&Bn[b_row0 * BS_STR + b_q0 * 4 + 3] = f2tf32(pb[0].w);
            *(uint32_t*)&Bn[b_row1 * BS_STR + b_q1 * 4 + 0] = f2tf32(pb[1].x);
            *(uint32_t*)&Bn[b_row1 * BS_STR + b_q1 * 4 + 1] = f2tf32(pb[1].y);
            *(uint32_t*)&Bn[b_row1 * BS_STR + b_q1 * 4 + 2] = f2tf32(pb[1].z);
            *(uint32_t*)&Bn[b_row1 * BS_STR + b_q1 * 4 + 3] = f2tf32(pb[1].w);
            __syncthreads();
            buf ^= 1;
        }
    }

#pragma unroll
    for (int mt = 0; mt < 4; mt++) {
#pragma unroll
        for (int nt = 0; nt < 4; nt++) {
            const int j  = n0 + wc * 32 + nt * 8 + tg * 2;
            const int h  = j >> 6, dd = j & 63;
            const float bj0 = bias[j], bj1 = bias[j + 1];
            const int m  = m0 + wr * 64 + mt * 16 + gp;
            const int bb = m >> 11, nn = m & 2047;
            float2 v0 = make_float2(c[mt][nt][0] + bj0, c[mt][nt][1] + bj1);
            float2 v1 = make_float2(c[mt][nt][2] + bj0, c[mt][nt][3] + bj1);
            float* base = outp + (((size_t)(bb * H_ + h)) * N_ + nn) * D_ + dd;
            *(float2*)base = v0;
            *(float2*)(base + 8 * (size_t)D_) = v1;
        }
    }
}

// ---------------------------------------------------------------------------
// tf32 flash attention v2: P in registers (V rows permuted), LDSM for K.
// CTA: 128 Q rows x one (b,h). 8 warps, warp = 16 rows x 64 KV cols.
// ---------------------------------------------------------------------------
#define KS_STR 68
#define VS_STR 72
#define FLASH_SMEM ((2*64*KS_STR + 2*64*VS_STR) * 4)   // 71680 B

__global__ __launch_bounds__(256)
void flash_mma(const float* __restrict__ gq, const float* __restrict__ gk,
               const float* __restrict__ gv, float* __restrict__ out)
{
    extern __shared__ __align__(16) uint32_t smu[];
    uint32_t* Ks = smu;                    // 2 x 64x68 (also Q staging: 128x68)
    uint32_t* Vs = Ks + 2 * 64 * KS_STR;   // 2 x 64x72 (rows permuted per 8-block)

    const int tid = threadIdx.x, lane = tid & 31, wid = tid >> 5;
    const int gp = lane >> 2, tg = lane & 3;
    const int qt = (int)gridDim.x - 1 - (int)blockIdx.x;  // heavy tiles first
    const int bh = blockIdx.y;
    const int n0 = qt * 128;
    const int nkt = 2 * qt + 2;

    const float* qb = gq + (size_t)bh * (N_ * D_);
    const float* kb = gk + (size_t)bh * (N_ * D_);
    const float* vb = gv + (size_t)bh * (N_ * D_);

    const float QSC = 0.125f * 1.4426950408889634f;  // scale * log2(e)

    // KV loader mapping: 4 threads per row, 16 floats each
    const int kr = tid >> 2, kc = (tid & 3) * 16;
    // permuted V row within its 8-block: kv offset c -> row (c&1 ? 4+(c>>1) : c>>1)
    const int vrow = (kr & ~7) | ((kr & 1) ? 4 + ((kr & 7) >> 1) : ((kr & 7) >> 1));

    // issue KV tile-0 global loads early (hide behind Q staging)
    float4 kreg[4], vreg[4];
    {
        const float* kp = kb + (size_t)kr * D_ + kc;
        const float* vp = vb + (size_t)kr * D_ + kc;
#pragma unroll
        for (int i = 0; i < 4; i++) {
            kreg[i] = *(const float4*)(kp + 4 * i);
            vreg[i] = *(const float4*)(vp + 4 * i);
        }
    }

    // stage Q (prescaled tf32) into the K area, grab fragments
    for (int idx = tid; idx < 128 * 16; idx += 256) {
        int r = idx >> 4, q = (idx & 15) * 4;
        float4 v = *(const float4*)(qb + (size_t)(n0 + r) * D_ + q);
        *(uint4*)(Ks + r * KS_STR + q) =
            make_uint4(f2tf32(v.x * QSC), f2tf32(v.y * QSC),
                       f2tf32(v.z * QSC), f2tf32(v.w * QSC));
    }
    __syncthreads();

    const int r0 = wid * 16 + gp;
    uint32_t qf[8][4];
#pragma unroll
    for (int ks = 0; ks < 8; ks++) {
        int k0 = ks * 8;
        qf[ks][0] = Ks[r0 * KS_STR + k0 + tg];
        qf[ks][1] = Ks[(r0 + 8) * KS_STR + k0 + tg];
        qf[ks][2] = Ks[r0 * KS_STR + k0 + tg + 4];
        qf[ks][3] = Ks[(r0 + 8) * KS_STR + k0 + tg + 4];
    }
    __syncthreads();

    // stage KV tile 0
    {
        uint32_t* kd = Ks + kr * KS_STR + kc;
        uint32_t* vd = Vs + vrow * VS_STR + kc;
#pragma unroll
        for (int i = 0; i < 4; i++) {
            *(uint4*)(kd + 4 * i) = make_uint4(f2tf32(kreg[i].x), f2tf32(kreg[i].y),
                                               f2tf32(kreg[i].z), f2tf32(kreg[i].w));
            *(uint4*)(vd + 4 * i) = make_uint4(f2tf32(vreg[i].x), f2tf32(vreg[i].y),
                                               f2tf32(vreg[i].z), f2tf32(vreg[i].w));
        }
    }
    __syncthreads();

    // ldmatrix lane address pieces for K b-fragments
    const int lrow  = lane & 7;
    const int lhalf = (lane >> 3) & 1;   // k half (0: cols k0..3, 1: k0+4..7)
    const int lnt   = (lane >> 4) & 1;   // nt within pair

    float m0r = -1e30f, m1r = -1e30f, l0 = 0.f, l1 = 0.f;
    float o[8][4];
#pragma unroll
    for (int nt = 0; nt < 8; nt++)
#pragma unroll
        for (int e = 0; e < 4; e++) o[nt][e] = 0.f;

    int buf = 0;
    for (int kt = 0; kt < nkt; kt++) {
        const int c0 = kt * 64;

        // --- S = Q K^T ---
        float s[8][4];
#pragma unroll
        for (int nt = 0; nt < 8; nt++)
#pragma unroll
            for (int e = 0; e < 4; e++) s[nt][e] = 0.f;

        const uint32_t kbase = smem_u32(Ks + buf * (64 * KS_STR)) +
                               (((lnt * 8 + lrow) * KS_STR + lhalf * 4) << 2);
#pragma unroll
        for (int n = 0; n < 4; n++) {
            const uint32_t an = kbase + ((n * 16 * KS_STR) << 2);  // pair base
#pragma unroll
            for (int ks = 0; ks < 8; ks++) {
                uint32_t b0a, b1a, b0b, b1b;
                ldsm_x4(b0a, b1a, b0b, b1b, an + (ks * 8 << 2));
                mma_tf32(s[2*n][0], s[2*n][1], s[2*n][2], s[2*n][3],
                         qf[ks][0], qf[ks][1], qf[ks][2], qf[ks][3], b0a, b1a);
                mma_tf32(s[2*n+1][0], s[2*n+1][1], s[2*n+1][2], s[2*n+1][3],
                         qf[ks][0], qf[ks][1], qf[ks][2], qf[ks][3], b0b, b1b);
            }
        }

        // --- causal mask (diagonal tiles only) ---
        if (kt >= 2 * qt) {
            const int i0g = n0 + r0, i1g = i0g + 8;
#pragma unroll
            for (int nt = 0; nt < 8; nt++) {
                const int j0 = c0 + nt * 8 + 2 * tg;
                if (j0     > i0g) s[nt][0] = -1e30f;
                if (j0 + 1 > i0g) s[nt][1] = -1e30f;
                if (j0     > i1g) s[nt][2] = -1e30f;
                if (j0 + 1 > i1g) s[nt][3] = -1e30f;
            }
        }

        // --- online softmax (log2 domain) ---
        float mx0 = -1e30f, mx1 = -1e30f;
#pragma unroll
        for (int nt = 0; nt < 8; nt++) {
            mx0 = fmaxf(mx0, fmaxf(s[nt][0], s[nt][1]));
            mx1 = fmaxf(mx1, fmaxf(s[nt][2], s[nt][3]));
        }
        mx0 = fmaxf(mx0, __shfl_xor_sync(0xffffffffu, mx0, 1));
        mx0 = fmaxf(mx0, __shfl_xor_sync(0xffffffffu, mx0, 2));
        mx1 = fmaxf(mx1, __shfl_xor_sync(0xffffffffu, mx1, 1));
        mx1 = fmaxf(mx1, __shfl_xor_sync(0xffffffffu, mx1, 2));

        const float mn0 = fmaxf(m0r, mx0), mn1 = fmaxf(m1r, mx1);
        const float al0 = ex2f(m0r - mn0), al1 = ex2f(m1r - mn1);
        m0r = mn0; m1r = mn1;

        float ls0 = 0.f, ls1 = 0.f;
#pragma unroll
        for (int nt = 0; nt < 8; nt++) {
            s[nt][0] = ex2f(s[nt][0] - mn0);
            s[nt][1] = ex2f(s[nt][1] - mn0);
            s[nt][2] = ex2f(s[nt][2] - mn1);
            s[nt][3] = ex2f(s[nt][3] - mn1);
            ls0 += s[nt][0] + s[nt][1];
            ls1 += s[nt][2] + s[nt][3];
        }
        ls0 += __shfl_xor_sync(0xffffffffu, ls0, 1);
        ls0 += __shfl_xor_sync(0xffffffffu, ls0, 2);
        ls1 += __shfl_xor_sync(0xffffffffu, ls1, 1);
        ls1 += __shfl_xor_sync(0xffffffffu, ls1, 2);
        l0 = l0 * al0 + ls0;
        l1 = l1 * al1 + ls1;
#pragma unroll
        for (int nt = 0; nt < 8; nt++) {
            o[nt][0] *= al0; o[nt][1] *= al0;
            o[nt][2] *= al1; o[nt][3] *= al1;
        }

        // --- prefetch next K/V tile into registers ---
        if (kt + 1 < nkt) {
            const float* kp = kb + (size_t)(c0 + 64 + kr) * D_ + kc;
            const float* vp = vb + (size_t)(c0 + 64 + kr) * D_ + kc;
#pragma unroll
            for (int i = 0; i < 4; i++) {
                kreg[i] = *(const float4*)(kp + 4 * i);
                vreg[i] = *(const float4*)(vp + 4 * i);
            }
        }

        // --- O += P V  (P = s regs directly as A-fragments; V rows permuted) ---
        const uint32_t* Vb = Vs + buf * (64 * VS_STR);
#pragma unroll
        for (int ks = 0; ks < 8; ks++) {
            const int k0 = ks * 8;
            const uint32_t a0 = f2tf32(s[ks][0]);   // (gp,   k=tg)   <- col 2tg
            const uint32_t a1 = f2tf32(s[ks][2]);   // (gp+8, k=tg)
            const uint32_t a2 = f2tf32(s[ks][1]);   // (gp,   k=tg+4) <- col 2tg+1
            const uint32_t a3 = f2tf32(s[ks][3]);   // (gp+8, k=tg+4)
            uint32_t b0[8], b1[8];
#pragma unroll
            for (int nt = 0; nt < 8; nt++) {
                b0[nt] = Vb[(k0 + tg) * VS_STR + nt * 8 + gp];
                b1[nt] = Vb[(k0 + tg + 4) * VS_STR + nt * 8 + gp];
            }
#pragma unroll
            for (int nt = 0; nt < 8; nt++)
                mma_tf32(o[nt][0], o[nt][1], o[nt][2], o[nt][3],
                         a0, a1, a2, a3, b0[nt], b1[nt]);
        }

        // --- stage next tile into the other buffer ---
        if (kt + 1 < nkt) {
            uint32_t* kd = Ks + (buf ^ 1) * (64 * KS_STR) + kr * KS_STR + kc;
            uint32_t* vd = Vs + (buf ^ 1) * (64 * VS_STR) + vrow * VS_STR + kc;
#pragma unroll
            for (int i = 0; i < 4; i++) {
                *(uint4*)(kd + 4 * i) = make_uint4(f2tf32(kreg[i].x), f2tf32(kreg[i].y),
                                                   f2tf32(kreg[i].z), f2tf32(kreg[i].w));
                *(uint4*)(vd + 4 * i) = make_uint4(f2tf32(vreg[i].x), f2tf32(vreg[i].y),
                                                   f2tf32(vreg[i].z), f2tf32(vreg[i].w));
            }
            __syncthreads();
            buf ^= 1;
        }
    }

    // --- normalize and write out [B, N, F] ---
    const float inv0 = 1.f / l0, inv1 = 1.f / l1;
    const int bb = bh >> 4, h = bh & 15;
    float* base = out + ((size_t)(bb * N_ + n0 + r0)) * F_ + h * D_;
#pragma unroll
    for (int nt = 0; nt < 8; nt++) {
        const int d = nt * 8 + 2 * tg;
        *(float2*)(base + d) = make_float2(o[nt][0] * inv0, o[nt][1] * inv0);
        *(float2*)(base + 8 * F_ + d) = make_float2(o[nt][2] * inv1, o[nt][3] * inv1);
    }
}

// ---------------------------------------------------------------------------
extern "C" void kernel_launch(void* const* d_in, const int* in_sizes, int n_in,
                              void* d_out, int out_size)
{
    const float* x  = (const float*)d_in[0];
    const float* Wq = (const float*)d_in[1];
    const float* bq = (const float*)d_in[2];
    const float* Wk = (const float*)d_in[3];
    const float* bk = (const float*)d_in[4];
    const float* Wv = (const float*)d_in[5];
    const float* bv = (const float*)d_in[6];
    float* out = (float*)d_out;
    (void)in_sizes; (void)n_in; (void)out_size;

    float *pq = nullptr, *pk = nullptr, *pv = nullptr;
    cudaGetSymbolAddress((void**)&pq, g_q);
    cudaGetSymbolAddress((void**)&pk, g_k);
    cudaGetSymbolAddress((void**)&pv, g_v);

    qkv_mma_gemm<<<dim3(F_ / 128, M_ / 128, 3), 256>>>(
        x, Wq, Wk, Wv, bq, bk, bv, pq, pk, pv);

    cudaFuncSetAttribute(flash_mma,
                         cudaFuncAttributeMaxDynamicSharedMemorySize, FLASH_SMEM);
    flash_mma<<<dim3(N_ / 128, B_ * H_), 256, FLASH_SMEM>>>(pq, pk, pv, out);
}

// round 7
// speedup vs baseline: 3.3831x; 1.0849x over previous
#include <cuda_runtime.h>
#include <math.h>
#include <stdint.h>

#define B_ 4
#define N_ 2048
#define F_ 1024
#define H_ 16
#define D_ 64
#define M_ (B_*N_)   // 8192 rows

// Scratch for Q/K/V in [b, h, n, d] layout.
// GEMM epilogue stores Q pre-scaled by 0.125*log2(e) and tf32-rounded;
// K and V tf32-rounded. Flash consumes raw bits (numerics identical to r5).
__device__ float g_q[(size_t)B_*H_*N_*D_];
__device__ float g_k[(size_t)B_*H_*N_*D_];
__device__ float g_v[(size_t)B_*H_*N_*D_];

__device__ __forceinline__ uint32_t f2tf32(float x) {
    uint32_t y;
    asm("cvt.rna.tf32.f32 %0, %1;" : "=r"(y) : "f"(x));
    return y;
}
__device__ __forceinline__ float ex2f(float x) {
    float y;
    asm("ex2.approx.ftz.f32 %0, %1;" : "=f"(y) : "f"(x));
    return y;
}
__device__ __forceinline__ uint32_t smem_u32(const void* p) {
    uint32_t a;
    asm("{ .reg .u64 t; cvta.to.shared.u64 t, %1; cvt.u32.u64 %0, t; }" : "=r"(a) : "l"(p));
    return a;
}
__device__ __forceinline__ void mma_tf32(float& d0, float& d1, float& d2, float& d3,
                                         uint32_t a0, uint32_t a1, uint32_t a2, uint32_t a3,
                                         uint32_t b0, uint32_t b1)
{
    asm volatile("mma.sync.aligned.m16n8k8.row.col.f32.tf32.tf32.f32 "
                 "{%0,%1,%2,%3}, {%4,%5,%6,%7}, {%8,%9}, {%0,%1,%2,%3};"
                 : "+f"(d0), "+f"(d1), "+f"(d2), "+f"(d3)
                 : "r"(a0), "r"(a1), "r"(a2), "r"(a3), "r"(b0), "r"(b1));
}
__device__ __forceinline__ void ldsm_x4(uint32_t& r0, uint32_t& r1, uint32_t& r2, uint32_t& r3,
                                        uint32_t addr)
{
    asm volatile("ldmatrix.sync.aligned.m8n8.x4.shared.b16 {%0,%1,%2,%3}, [%4];"
                 : "=r"(r0), "=r"(r1), "=r"(r2), "=r"(r3) : "r"(addr));
}
#define CP_ASYNC16(dst, src) \
    asm volatile("cp.async.cg.shared.global [%0], [%1], 16;" :: "r"(dst), "l"(src) : "memory")
#define CP_COMMIT() asm volatile("cp.async.commit_group;" ::: "memory")
#define CP_WAIT0()  asm volatile("cp.async.wait_group 0;" ::: "memory")

#define QSC_ 0.18033688011112042f   // 0.125 * log2(e)

// ---------------------------------------------------------------------------
// tf32 tensor-core GEMM. Epilogue tf32-rounds outputs (Q also pre-scaled).
// ---------------------------------------------------------------------------
#define BK 16
#define AS_STR 20
#define BS_STR 136

__global__ __launch_bounds__(256, 2)
void qkv_mma_gemm(const float* __restrict__ X,
                  const float* __restrict__ W0, const float* __restrict__ W1,
                  const float* __restrict__ W2,
                  const float* __restrict__ bi0, const float* __restrict__ bi1,
                  const float* __restrict__ bi2,
                  float* __restrict__ o0, float* __restrict__ o1,
                  float* __restrict__ o2)
{
    __shared__ float As[2][128 * AS_STR];
    __shared__ float Bs[2][BK * BS_STR];

    const int z = blockIdx.z;
    const float* W    = (z == 0) ? W0 : (z == 1) ? W1 : W2;
    const float* bias = (z == 0) ? bi0 : (z == 1) ? bi1 : bi2;
    float* outp       = (z == 0) ? o0 : (z == 1) ? o1 : o2;
    const float sc    = (z == 0) ? QSC_ : 1.0f;

    const int tid  = threadIdx.x;
    const int lane = tid & 31;
    const int wid  = tid >> 5;
    const int wr   = wid & 1;
    const int wc   = wid >> 1;
    const int m0   = blockIdx.y * 128;
    const int n0   = blockIdx.x * 128;
    const int tg   = lane & 3;
    const int gp   = lane >> 2;

    float4 pa[2], pb[2];
    const int a_row0 = tid >> 2,  a_q0 = tid & 3;
    const int a_row1 = (tid + 256) >> 2, a_q1 = (tid + 256) & 3;
    const int b_row0 = tid >> 5,  b_q0 = tid & 31;
    const int b_row1 = (tid + 256) >> 5, b_q1 = (tid + 256) & 31;

    float c[4][4][4];
#pragma unroll
    for (int i = 0; i < 4; i++)
#pragma unroll
        for (int j = 0; j < 4; j++)
#pragma unroll
            for (int r = 0; r < 4; r++) c[i][j][r] = 0.f;

    pa[0] = *(const float4*)&X[(size_t)(m0 + a_row0) * F_ + a_q0 * 4];
    pa[1] = *(const float4*)&X[(size_t)(m0 + a_row1) * F_ + a_q1 * 4];
    pb[0] = *(const float4*)&W[(size_t)b_row0 * F_ + n0 + b_q0 * 4];
    pb[1] = *(const float4*)&W[(size_t)b_row1 * F_ + n0 + b_q1 * 4];

    int buf = 0;
    {
        float* A = As[0]; float* Bsm = Bs[0];
        *(uint32_t*)&A[a_row0 * AS_STR + a_q0 * 4 + 0] = f2tf32(pa[0].x);
        *(uint32_t*)&A[a_row0 * AS_STR + a_q0 * 4 + 1] = f2tf32(pa[0].y);
        *(uint32_t*)&A[a_row0 * AS_STR + a_q0 * 4 + 2] = f2tf32(pa[0].z);
        *(uint32_t*)&A[a_row0 * AS_STR + a_q0 * 4 + 3] = f2tf32(pa[0].w);
        *(uint32_t*)&A[a_row1 * AS_STR + a_q1 * 4 + 0] = f2tf32(pa[1].x);
        *(uint32_t*)&A[a_row1 * AS_STR + a_q1 * 4 + 1] = f2tf32(pa[1].y);
        *(uint32_t*)&A[a_row1 * AS_STR + a_q1 * 4 + 2] = f2tf32(pa[1].z);
        *(uint32_t*)&A[a_row1 * AS_STR + a_q1 * 4 + 3] = f2tf32(pa[1].w);
        *(uint32_t*)&Bsm[b_row0 * BS_STR + b_q0 * 4 + 0] = f2tf32(pb[0].x);
        *(uint32_t*)&Bsm[b_row0 * BS_STR + b_q0 * 4 + 1] = f2tf32(pb[0].y);
        *(uint32_t*)&Bsm[b_row0 * BS_STR + b_q0 * 4 + 2] = f2tf32(pb[0].z);
        *(uint32_t*)&Bsm[b_row0 * BS_STR + b_q0 * 4 + 3] = f2tf32(pb[0].w);
        *(uint32_t*)&Bsm[b_row1 * BS_STR + b_q1 * 4 + 0] = f2tf32(pb[1].x);
        *(uint32_t*)&Bsm[b_row1 * BS_STR + b_q1 * 4 + 1] = f2tf32(pb[1].y);
        *(uint32_t*)&Bsm[b_row1 * BS_STR + b_q1 * 4 + 2] = f2tf32(pb[1].z);
        *(uint32_t*)&Bsm[b_row1 * BS_STR + b_q1 * 4 + 3] = f2tf32(pb[1].w);
    }
    __syncthreads();

    const int NT = F_ / BK;
    for (int kt = 0; kt < NT; kt++) {
        if (kt + 1 < NT) {
            const int kb2 = (kt + 1) * BK;
            pa[0] = *(const float4*)&X[(size_t)(m0 + a_row0) * F_ + kb2 + a_q0 * 4];
            pa[1] = *(const float4*)&X[(size_t)(m0 + a_row1) * F_ + kb2 + a_q1 * 4];
            pb[0] = *(const float4*)&W[(size_t)(kb2 + b_row0) * F_ + n0 + b_q0 * 4];
            pb[1] = *(const float4*)&W[(size_t)(kb2 + b_row1) * F_ + n0 + b_q1 * 4];
        }

        const uint32_t* A = (const uint32_t*)As[buf];
        const uint32_t* Bm = (const uint32_t*)Bs[buf];
#pragma unroll
        for (int kk = 0; kk < BK; kk += 8) {
            uint32_t af[4][4], bf[4][2];
#pragma unroll
            for (int mt = 0; mt < 4; mt++) {
                const int r = wr * 64 + mt * 16 + gp;
                af[mt][0] = A[(r    ) * AS_STR + kk + tg    ];
                af[mt][1] = A[(r + 8) * AS_STR + kk + tg    ];
                af[mt][2] = A[(r    ) * AS_STR + kk + tg + 4];
                af[mt][3] = A[(r + 8) * AS_STR + kk + tg + 4];
            }
#pragma unroll
            for (int nt = 0; nt < 4; nt++) {
                const int col = wc * 32 + nt * 8 + gp;
                bf[nt][0] = Bm[(kk + tg    ) * BS_STR + col];
                bf[nt][1] = Bm[(kk + tg + 4) * BS_STR + col];
            }
#pragma unroll
            for (int mt = 0; mt < 4; mt++)
#pragma unroll
                for (int nt = 0; nt < 4; nt++)
                    mma_tf32(c[mt][nt][0], c[mt][nt][1], c[mt][nt][2], c[mt][nt][3],
                             af[mt][0], af[mt][1], af[mt][2], af[mt][3],
                             bf[nt][0], bf[nt][1]);
        }
        __syncthreads();

        if (kt + 1 < NT) {
            float* An = As[buf ^ 1]; float* Bn = Bs[buf ^ 1];
            *(uint32_t*)&An[a_row0 * AS_STR + a_q0 * 4 + 0] = f2tf32(pa[0].x);
            *(uint32_t*)&An[a_row0 * AS_STR + a_q0 * 4 + 1] = f2tf32(pa[0].y);
            *(uint32_t*)&An[a_row0 * AS_STR + a_q0 * 4 + 2] = f2tf32(pa[0].z);
            *(uint32_t*)&An[a_row0 * AS_STR + a_q0 * 4 + 3] = f2tf32(pa[0].w);
            *(uint32_t*)&An[a_row1 * AS_STR + a_q1 * 4 + 0] = f2tf32(pa[1].x);
            *(uint32_t*)&An[a_row1 * AS_STR + a_q1 * 4 + 1] = f2tf32(pa[1].y);
            *(uint32_t*)&An[a_row1 * AS_STR + a_q1 * 4 + 2] = f2tf32(pa[1].z);
            *(uint32_t*)&An[a_row1 * AS_STR + a_q1 * 4 + 3] = f2tf32(pa[1].w);
            *(uint32_t*)&Bn[b_row0 * BS_STR + b_q0 * 4 + 0] = f2tf32(pb[0].x);
            *(uint32_t*)&Bn[b_row0 * BS_STR + b_q0 * 4 + 1] = f2tf32(pb[0].y);
            *(uint32_t*)&Bn[b_row0 * BS_STR + b_q0 * 4 + 2] = f2tf32(pb[0].z);
            *(uint32_t*)&Bn[b_row0 * BS_STR + b_q0 * 4 + 3] = f2tf32(pb[0].w);
            *(uint32_t*)&Bn[b_row1 * BS_STR + b_q1 * 4 + 0] = f2tf32(pb[1].x);
            *(uint32_t*)&Bn[b_row1 * BS_STR + b_q1 * 4 + 1] = f2tf32(pb[1].y);
            *(uint32_t*)&Bn[b_row1 * BS_STR + b_q1 * 4 + 2] = f2tf32(pb[1].z);
            *(uint32_t*)&Bn[b_row1 * BS_STR + b_q1 * 4 + 3] = f2tf32(pb[1].w);
            __syncthreads();
            buf ^= 1;
        }
    }

    // epilogue: bias, optional Q prescale, tf32 rounding (moved from flash)
#pragma unroll
    for (int mt = 0; mt < 4; mt++) {
#pragma unroll
        for (int nt = 0; nt < 4; nt++) {
            const int j  = n0 + wc * 32 + nt * 8 + tg * 2;
            const int h  = j >> 6, dd = j & 63;
            const float bj0 = bias[j], bj1 = bias[j + 1];
            const int m  = m0 + wr * 64 + mt * 16 + gp;
            const int bb = m >> 11, nn = m & 2047;
            float2 v0 = make_float2(
                __uint_as_float(f2tf32((c[mt][nt][0] + bj0) * sc)),
                __uint_as_float(f2tf32((c[mt][nt][1] + bj1) * sc)));
            float2 v1 = make_float2(
                __uint_as_float(f2tf32((c[mt][nt][2] + bj0) * sc)),
                __uint_as_float(f2tf32((c[mt][nt][3] + bj1) * sc)));
            float* base = outp + (((size_t)(bb * H_ + h)) * N_ + nn) * D_ + dd;
            *(float2*)base = v0;
            *(float2*)(base + 8 * (size_t)D_) = v1;
        }
    }
}

// ---------------------------------------------------------------------------
// tf32 flash attention v3: cp.async staging, V transposed+column-permuted in
// smem, LDSM everywhere, 2 CTAs/SM (<=128 regs).
// VT_STR must keep LDSM row addresses 16B-aligned: stride*4 % 16 == 0.
// ---------------------------------------------------------------------------
#define QS_STR 68
#define KS_STR 68
#define VT_STR 68
#define FLASH_SMEM ((128*QS_STR + 2*64*KS_STR + 2*64*VT_STR) * 4)  // 104448 B

__global__ __launch_bounds__(256, 2)
void flash_mma(const float* __restrict__ gq, const float* __restrict__ gk,
               const float* __restrict__ gv, float* __restrict__ out)
{
    extern __shared__ __align__(16) uint32_t smu[];
    uint32_t* Qs = smu;                       // 128 x 68 (raw tf32 bits)
    uint32_t* Ks = Qs + 128 * QS_STR;         // 2 x 64 x 68
    uint32_t* Vt = Ks + 2 * 64 * KS_STR;      // 2 x 64(d) x 68, cols kv-permuted

    const int tid = threadIdx.x, lane = tid & 31, wid = tid >> 5;
    const int gp = lane >> 2, tg = lane & 3;
    const int qt = (int)gridDim.x - 1 - (int)blockIdx.x;  // heavy tiles first
    const int bh = blockIdx.y;
    const int n0 = qt * 128;
    const int nkt = 2 * qt + 2;

    const float* qb = gq + (size_t)bh * (N_ * D_);
    const float* kb = gk + (size_t)bh * (N_ * D_);
    const float* vb = gv + (size_t)bh * (N_ * D_);

    const uint32_t qs_base = smem_u32(Qs);
    const uint32_t ks_base = smem_u32(Ks);
    const uint32_t vt_base = smem_u32(Vt);

    // loader mappings
    const int kr = tid >> 2, kc = (tid & 3) * 16;      // KV: 4 thr/row, 16 fl each
    // sigma^{-1}: V kv-row kr stored at smem column vcol (within its 8-block)
    const int vcol = (kr & ~7) | ((kr & 1) ? 4 + ((kr & 7) >> 1) : ((kr & 7) >> 1));

    // --- prologue: cp.async Q (8x16B/thr) + K tile0 (4x16B/thr); V tile0 LDG ---
    {
        const int qr = tid >> 1, qc0 = (tid & 1) * 32;
        const float* src = qb + (size_t)(n0 + qr) * D_ + qc0;
        uint32_t dst = qs_base + ((qr * QS_STR + qc0) << 2);
#pragma unroll
        for (int i = 0; i < 8; i++) CP_ASYNC16(dst + 16 * i, src + 4 * i);
    }
    {
        const float* src = kb + (size_t)kr * D_ + kc;
        uint32_t dst = ks_base + ((kr * KS_STR + kc) << 2);
#pragma unroll
        for (int i = 0; i < 4; i++) CP_ASYNC16(dst + 16 * i, src + 4 * i);
    }
    CP_COMMIT();

    float4 vreg[4];
    {
        const float* vp = vb + (size_t)kr * D_ + kc;
#pragma unroll
        for (int i = 0; i < 4; i++) vreg[i] = *(const float4*)(vp + 4 * i);
    }

    CP_WAIT0();
    __syncthreads();

    // Q fragments via LDSM (held in regs for the whole kernel)
    uint32_t qf[8][4];
    {
        const int qrow = wid * 16 + ((lane >> 3) & 1) * 8 + (lane & 7);
        const int qcol = ((lane >> 4) & 1) * 4;
        const uint32_t qaddr = qs_base + ((qrow * QS_STR + qcol) << 2);
#pragma unroll
        for (int ks = 0; ks < 8; ks++)
            ldsm_x4(qf[ks][0], qf[ks][1], qf[ks][2], qf[ks][3],
                    qaddr + ((ks * 8) << 2));
    }

    // stage Vt tile0 (transposed, column-permuted)
    {
        uint32_t* vd = Vt;
#pragma unroll
        for (int j = 0; j < 4; j++) {
            vd[(kc + 4 * j + 0) * VT_STR + vcol] = __float_as_uint(vreg[j].x);
            vd[(kc + 4 * j + 1) * VT_STR + vcol] = __float_as_uint(vreg[j].y);
            vd[(kc + 4 * j + 2) * VT_STR + vcol] = __float_as_uint(vreg[j].z);
            vd[(kc + 4 * j + 3) * VT_STR + vcol] = __float_as_uint(vreg[j].w);
        }
    }
    __syncthreads();

    // LDSM lane-address pieces (shared form for K and Vt)
    const int lrow8 = ((lane >> 4) & 1) * 8 + (lane & 7);   // row-within-16 block
    const int lcol4 = ((lane >> 3) & 1) * 4;                // k half

    float m0r = -1e30f, m1r = -1e30f, l0 = 0.f, l1 = 0.f;
    float o[8][4];
#pragma unroll
    for (int nt = 0; nt < 8; nt++)
#pragma unroll
        for (int e = 0; e < 4; e++) o[nt][e] = 0.f;

    int buf = 0;
    for (int kt = 0; kt < nkt; kt++) {
        const int c0 = kt * 64;
        const int more = (kt + 1 < nkt);

        // issue cp.async for K(t+1)
        if (more) {
            const float* src = kb + (size_t)(c0 + 64 + kr) * D_ + kc;
            uint32_t dst = ks_base + (((buf ^ 1) * 64 * KS_STR + kr * KS_STR + kc) << 2);
#pragma unroll
            for (int i = 0; i < 4; i++) CP_ASYNC16(dst + 16 * i, src + 4 * i);
            CP_COMMIT();
        }

        // --- S = Q K^T ---
        float s[8][4];
#pragma unroll
        for (int nt = 0; nt < 8; nt++)
#pragma unroll
            for (int e = 0; e < 4; e++) s[nt][e] = 0.f;

        const uint32_t kaddr = ks_base +
            ((buf * 64 * KS_STR + lrow8 * KS_STR + lcol4) << 2);
#pragma unroll
        for (int n = 0; n < 4; n++) {
            const uint32_t an = kaddr + ((n * 16 * KS_STR) << 2);
#pragma unroll
            for (int ks = 0; ks < 8; ks++) {
                uint32_t b0a, b1a, b0b, b1b;
                ldsm_x4(b0a, b1a, b0b, b1b, an + ((ks * 8) << 2));
                mma_tf32(s[2*n][0], s[2*n][1], s[2*n][2], s[2*n][3],
                         qf[ks][0], qf[ks][1], qf[ks][2], qf[ks][3], b0a, b1a);
                mma_tf32(s[2*n+1][0], s[2*n+1][1], s[2*n+1][2], s[2*n+1][3],
                         qf[ks][0], qf[ks][1], qf[ks][2], qf[ks][3], b0b, b1b);
            }
        }

        // --- causal mask (diagonal tiles only) ---
        const int r0 = wid * 16 + gp;
        if (kt >= 2 * qt) {
            const int i0g = n0 + r0, i1g = i0g + 8;
#pragma unroll
            for (int nt = 0; nt < 8; nt++) {
                const int j0 = c0 + nt * 8 + 2 * tg;
                if (j0     > i0g) s[nt][0] = -1e30f;
                if (j0 + 1 > i0g) s[nt][1] = -1e30f;
                if (j0     > i1g) s[nt][2] = -1e30f;
                if (j0 + 1 > i1g) s[nt][3] = -1e30f;
            }
        }

        // --- online softmax (log2 domain) ---
        float mx0 = -1e30f, mx1 = -1e30f;
#pragma unroll
        for (int nt = 0; nt < 8; nt++) {
            mx0 = fmaxf(mx0, fmaxf(s[nt][0], s[nt][1]));
            mx1 = fmaxf(mx1, fmaxf(s[nt][2], s[nt][3]));
        }
        mx0 = fmaxf(mx0, __shfl_xor_sync(0xffffffffu, mx0, 1));
        mx0 = fmaxf(mx0, __shfl_xor_sync(0xffffffffu, mx0, 2));
        mx1 = fmaxf(mx1, __shfl_xor_sync(0xffffffffu, mx1, 1));
        mx1 = fmaxf(mx1, __shfl_xor_sync(0xffffffffu, mx1, 2));

        const float mn0 = fmaxf(m0r, mx0), mn1 = fmaxf(m1r, mx1);
        const float al0 = ex2f(m0r - mn0), al1 = ex2f(m1r - mn1);
        m0r = mn0; m1r = mn1;

        float ls0 = 0.f, ls1 = 0.f;
#pragma unroll
        for (int nt = 0; nt < 8; nt++) {
            s[nt][0] = ex2f(s[nt][0] - mn0);
            s[nt][1] = ex2f(s[nt][1] - mn0);
            s[nt][2] = ex2f(s[nt][2] - mn1);
            s[nt][3] = ex2f(s[nt][3] - mn1);
            ls0 += s[nt][0] + s[nt][1];
            ls1 += s[nt][2] + s[nt][3];
        }
        ls0 += __shfl_xor_sync(0xffffffffu, ls0, 1);
        ls0 += __shfl_xor_sync(0xffffffffu, ls0, 2);
        ls1 += __shfl_xor_sync(0xffffffffu, ls1, 1);
        ls1 += __shfl_xor_sync(0xffffffffu, ls1, 2);
        l0 = l0 * al0 + ls0;
        l1 = l1 * al1 + ls1;
#pragma unroll
        for (int nt = 0; nt < 8; nt++) {
            o[nt][0] *= al0; o[nt][1] *= al0;
            o[nt][2] *= al1; o[nt][3] *= al1;
        }

        // --- V(t+1) global loads (covered by PV below) ---
        if (more) {
            const float* vp = vb + (size_t)(c0 + 64 + kr) * D_ + kc;
#pragma unroll
            for (int i = 0; i < 4; i++) vreg[i] = *(const float4*)(vp + 4 * i);
        }

        // --- O += P V  (P regs as a-frags; Vt column-permuted matches) ---
        const uint32_t vaddr = vt_base +
            ((buf * 64 * VT_STR + lrow8 * VT_STR + lcol4) << 2);
#pragma unroll
        for (int ks = 0; ks < 8; ks++) {
            const uint32_t a0 = f2tf32(s[ks][0]);
            const uint32_t a1 = f2tf32(s[ks][2]);
            const uint32_t a2 = f2tf32(s[ks][1]);
            const uint32_t a3 = f2tf32(s[ks][3]);
#pragma unroll
            for (int n = 0; n < 4; n++) {
                uint32_t b0a, b1a, b0b, b1b;
                ldsm_x4(b0a, b1a, b0b, b1b,
                        vaddr + ((n * 16 * VT_STR + ks * 8) << 2));
                mma_tf32(o[2*n][0], o[2*n][1], o[2*n][2], o[2*n][3],
                         a0, a1, a2, a3, b0a, b1a);
                mma_tf32(o[2*n+1][0], o[2*n+1][1], o[2*n+1][2], o[2*n+1][3],
                         a0, a1, a2, a3, b0b, b1b);
            }
        }

        // --- stage Vt(t+1); wait K(t+1); flip ---
        if (more) {
            uint32_t* vd = Vt + (buf ^ 1) * 64 * VT_STR;
#pragma unroll
            for (int j = 0; j < 4; j++) {
                vd[(kc + 4 * j + 0) * VT_STR + vcol] = __float_as_uint(vreg[j].x);
                vd[(kc + 4 * j + 1) * VT_STR + vcol] = __float_as_uint(vreg[j].y);
                vd[(kc + 4 * j + 2) * VT_STR + vcol] = __float_as_uint(vreg[j].z);
                vd[(kc + 4 * j + 3) * VT_STR + vcol] = __float_as_uint(vreg[j].w);
            }
            CP_WAIT0();
            __syncthreads();
            buf ^= 1;
        }
    }

    // --- normalize and write out [B, N, F] ---
    const int r0 = wid * 16 + gp;
    const float inv0 = 1.f / l0, inv1 = 1.f / l1;
    const int bb = bh >> 4, h = bh & 15;
    float* base = out + ((size_t)(bb * N_ + n0 + r0)) * F_ + h * D_;
#pragma unroll
    for (int nt = 0; nt < 8; nt++) {
        const int d = nt * 8 + 2 * tg;
        *(float2*)(base + d) = make_float2(o[nt][0] * inv0, o[nt][1] * inv0);
        *(float2*)(base + 8 * F_ + d) = make_float2(o[nt][2] * inv1, o[nt][3] * inv1);
    }
}

// ---------------------------------------------------------------------------
extern "C" void kernel_launch(void* const* d_in, const int* in_sizes, int n_in,
                              void* d_out, int out_size)
{
    const float* x  = (const float*)d_in[0];
    const float* Wq = (const float*)d_in[1];
    const float* bq = (const float*)d_in[2];
    const float* Wk = (const float*)d_in[3];
    const float* bk = (const float*)d_in[4];
    const float* Wv = (const float*)d_in[5];
    const float* bv = (const float*)d_in[6];
    float* out = (float*)d_out;
    (void)in_sizes; (void)n_in; (void)out_size;

    float *pq = nullptr, *pk = nullptr, *pv = nullptr;
    cudaGetSymbolAddress((void**)&pq, g_q);
    cudaGetSymbolAddress((void**)&pk, g_k);
    cudaGetSymbolAddress((void**)&pv, g_v);

    qkv_mma_gemm<<<dim3(F_ / 128, M_ / 128, 3), 256>>>(
        x, Wq, Wk, Wv, bq, bk, bv, pq, pk, pv);

    cudaFuncSetAttribute(flash_mma,
                         cudaFuncAttributeMaxDynamicSharedMemorySize, FLASH_SMEM);
    flash_mma<<<dim3(N_ / 128, B_ * H_), 256, FLASH_SMEM>>>(pq, pk, pv, out);
}

// round 8
// speedup vs baseline: 3.4805x; 1.0288x over previous
#include <cuda_runtime.h>
#include <math.h>
#include <stdint.h>

#define B_ 4
#define N_ 2048
#define F_ 1024
#define H_ 16
#define D_ 64
#define M_ (B_*N_)   // 8192 rows

// Scratch. g_q/g_k: [b,h,n,d]; g_v: TRANSPOSED [b,h,d,n].
// GEMM epilogue stores Q pre-scaled by 0.125*log2(e), all three tf32-rounded.
__device__ float g_q[(size_t)B_*H_*N_*D_];
__device__ float g_k[(size_t)B_*H_*N_*D_];
__device__ float g_v[(size_t)B_*H_*N_*D_];

__device__ __forceinline__ uint32_t f2tf32(float x) {
    uint32_t y;
    asm("cvt.rna.tf32.f32 %0, %1;" : "=r"(y) : "f"(x));
    return y;
}
__device__ __forceinline__ float ex2f(float x) {
    float y;
    asm("ex2.approx.ftz.f32 %0, %1;" : "=f"(y) : "f"(x));
    return y;
}
__device__ __forceinline__ uint32_t smem_u32(const void* p) {
    uint32_t a;
    asm("{ .reg .u64 t; cvta.to.shared.u64 t, %1; cvt.u32.u64 %0, t; }" : "=r"(a) : "l"(p));
    return a;
}
__device__ __forceinline__ void mma_tf32(float& d0, float& d1, float& d2, float& d3,
                                         uint32_t a0, uint32_t a1, uint32_t a2, uint32_t a3,
                                         uint32_t b0, uint32_t b1)
{
    asm volatile("mma.sync.aligned.m16n8k8.row.col.f32.tf32.tf32.f32 "
                 "{%0,%1,%2,%3}, {%4,%5,%6,%7}, {%8,%9}, {%0,%1,%2,%3};"
                 : "+f"(d0), "+f"(d1), "+f"(d2), "+f"(d3)
                 : "r"(a0), "r"(a1), "r"(a2), "r"(a3), "r"(b0), "r"(b1));
}
__device__ __forceinline__ void ldsm_x4(uint32_t& r0, uint32_t& r1, uint32_t& r2, uint32_t& r3,
                                        uint32_t addr)
{
    asm volatile("ldmatrix.sync.aligned.m8n8.x4.shared.b16 {%0,%1,%2,%3}, [%4];"
                 : "=r"(r0), "=r"(r1), "=r"(r2), "=r"(r3) : "r"(addr));
}
#define CP_ASYNC16(dst, src) \
    asm volatile("cp.async.cg.shared.global [%0], [%1], 16;" :: "r"(dst), "l"(src) : "memory")
#define CP_COMMIT() asm volatile("cp.async.commit_group;" ::: "memory")
#define CP_WAIT0()  asm volatile("cp.async.wait_group 0;" ::: "memory")

#define QSC_ 0.18033688011112042f   // 0.125 * log2(e)

// ---------------------------------------------------------------------------
// tf32 tensor-core GEMM. Epilogue tf32-rounds; Q pre-scaled; V transposed.
// ---------------------------------------------------------------------------
#define BK 16
#define AS_STR 20
#define BS_STR 136

__global__ __launch_bounds__(256, 2)
void qkv_mma_gemm(const float* __restrict__ X,
                  const float* __restrict__ W0, const float* __restrict__ W1,
                  const float* __restrict__ W2,
                  const float* __restrict__ bi0, const float* __restrict__ bi1,
                  const float* __restrict__ bi2,
                  float* __restrict__ o0, float* __restrict__ o1,
                  float* __restrict__ o2)
{
    __shared__ float As[2][128 * AS_STR];
    __shared__ float Bs[2][BK * BS_STR];

    const int z = blockIdx.z;
    const float* W    = (z == 0) ? W0 : (z == 1) ? W1 : W2;
    const float* bias = (z == 0) ? bi0 : (z == 1) ? bi1 : bi2;
    float* outp       = (z == 0) ? o0 : (z == 1) ? o1 : o2;
    const float sc    = (z == 0) ? QSC_ : 1.0f;

    const int tid  = threadIdx.x;
    const int lane = tid & 31;
    const int wid  = tid >> 5;
    const int wr   = wid & 1;
    const int wc   = wid >> 1;
    const int m0   = blockIdx.y * 128;
    const int n0   = blockIdx.x * 128;
    const int tg   = lane & 3;
    const int gp   = lane >> 2;

    float4 pa[2], pb[2];
    const int a_row0 = tid >> 2,  a_q0 = tid & 3;
    const int a_row1 = (tid + 256) >> 2, a_q1 = (tid + 256) & 3;
    const int b_row0 = tid >> 5,  b_q0 = tid & 31;
    const int b_row1 = (tid + 256) >> 5, b_q1 = (tid + 256) & 31;

    float c[4][4][4];
#pragma unroll
    for (int i = 0; i < 4; i++)
#pragma unroll
        for (int j = 0; j < 4; j++)
#pragma unroll
            for (int r = 0; r < 4; r++) c[i][j][r] = 0.f;

    pa[0] = *(const float4*)&X[(size_t)(m0 + a_row0) * F_ + a_q0 * 4];
    pa[1] = *(const float4*)&X[(size_t)(m0 + a_row1) * F_ + a_q1 * 4];
    pb[0] = *(const float4*)&W[(size_t)b_row0 * F_ + n0 + b_q0 * 4];
    pb[1] = *(const float4*)&W[(size_t)b_row1 * F_ + n0 + b_q1 * 4];

    int buf = 0;
    {
        float* A = As[0]; float* Bsm = Bs[0];
        *(uint32_t*)&A[a_row0 * AS_STR + a_q0 * 4 + 0] = f2tf32(pa[0].x);
        *(uint32_t*)&A[a_row0 * AS_STR + a_q0 * 4 + 1] = f2tf32(pa[0].y);
        *(uint32_t*)&A[a_row0 * AS_STR + a_q0 * 4 + 2] = f2tf32(pa[0].z);
        *(uint32_t*)&A[a_row0 * AS_STR + a_q0 * 4 + 3] = f2tf32(pa[0].w);
        *(uint32_t*)&A[a_row1 * AS_STR + a_q1 * 4 + 0] = f2tf32(pa[1].x);
        *(uint32_t*)&A[a_row1 * AS_STR + a_q1 * 4 + 1] = f2tf32(pa[1].y);
        *(uint32_t*)&A[a_row1 * AS_STR + a_q1 * 4 + 2] = f2tf32(pa[1].z);
        *(uint32_t*)&A[a_row1 * AS_STR + a_q1 * 4 + 3] = f2tf32(pa[1].w);
        *(uint32_t*)&Bsm[b_row0 * BS_STR + b_q0 * 4 + 0] = f2tf32(pb[0].x);
        *(uint32_t*)&Bsm[b_row0 * BS_STR + b_q0 * 4 + 1] = f2tf32(pb[0].y);
        *(uint32_t*)&Bsm[b_row0 * BS_STR + b_q0 * 4 + 2] = f2tf32(pb[0].z);
        *(uint32_t*)&Bsm[b_row0 * BS_STR + b_q0 * 4 + 3] = f2tf32(pb[0].w);
        *(uint32_t*)&Bsm[b_row1 * BS_STR + b_q1 * 4 + 0] = f2tf32(pb[1].x);
        *(uint32_t*)&Bsm[b_row1 * BS_STR + b_q1 * 4 + 1] = f2tf32(pb[1].y);
        *(uint32_t*)&Bsm[b_row1 * BS_STR + b_q1 * 4 + 2] = f2tf32(pb[1].z);
        *(uint32_t*)&Bsm[b_row1 * BS_STR + b_q1 * 4 + 3] = f2tf32(pb[1].w);
    }
    __syncthreads();

    const int NT = F_ / BK;
    for (int kt = 0; kt < NT; kt++) {
        if (kt + 1 < NT) {
            const int kb2 = (kt + 1) * BK;
            pa[0] = *(const float4*)&X[(size_t)(m0 + a_row0) * F_ + kb2 + a_q0 * 4];
            pa[1] = *(const float4*)&X[(size_t)(m0 + a_row1) * F_ + kb2 + a_q1 * 4];
            pb[0] = *(const float4*)&W[(size_t)(kb2 + b_row0) * F_ + n0 + b_q0 * 4];
            pb[1] = *(const float4*)&W[(size_t)(kb2 + b_row1) * F_ + n0 + b_q1 * 4];
        }

        const uint32_t* A = (const uint32_t*)As[buf];
        const uint32_t* Bm = (const uint32_t*)Bs[buf];
#pragma unroll
        for (int kk = 0; kk < BK; kk += 8) {
            uint32_t af[4][4], bf[4][2];
#pragma unroll
            for (int mt = 0; mt < 4; mt++) {
                const int r = wr * 64 + mt * 16 + gp;
                af[mt][0] = A[(r    ) * AS_STR + kk + tg    ];
                af[mt][1] = A[(r + 8) * AS_STR + kk + tg    ];
                af[mt][2] = A[(r    ) * AS_STR + kk + tg + 4];
                af[mt][3] = A[(r + 8) * AS_STR + kk + tg + 4];
            }
#pragma unroll
            for (int nt = 0; nt < 4; nt++) {
                const int col = wc * 32 + nt * 8 + gp;
                bf[nt][0] = Bm[(kk + tg    ) * BS_STR + col];
                bf[nt][1] = Bm[(kk + tg + 4) * BS_STR + col];
            }
#pragma unroll
            for (int mt = 0; mt < 4; mt++)
#pragma unroll
                for (int nt = 0; nt < 4; nt++)
                    mma_tf32(c[mt][nt][0], c[mt][nt][1], c[mt][nt][2], c[mt][nt][3],
                             af[mt][0], af[mt][1], af[mt][2], af[mt][3],
                             bf[nt][0], bf[nt][1]);
        }
        __syncthreads();

        if (kt + 1 < NT) {
            float* An = As[buf ^ 1]; float* Bn = Bs[buf ^ 1];
            *(uint32_t*)&An[a_row0 * AS_STR + a_q0 * 4 + 0] = f2tf32(pa[0].x);
            *(uint32_t*)&An[a_row0 * AS_STR + a_q0 * 4 + 1] = f2tf32(pa[0].y);
            *(uint32_t*)&An[a_row0 * AS_STR + a_q0 * 4 + 2] = f2tf32(pa[0].z);
            *(uint32_t*)&An[a_row0 * AS_STR + a_q0 * 4 + 3] = f2tf32(pa[0].w);
            *(uint32_t*)&An[a_row1 * AS_STR + a_q1 * 4 + 0] = f2tf32(pa[1].x);
            *(uint32_t*)&An[a_row1 * AS_STR + a_q1 * 4 + 1] = f2tf32(pa[1].y);
            *(uint32_t*)&An[a_row1 * AS_STR + a_q1 * 4 + 2] = f2tf32(pa[1].z);
            *(uint32_t*)&An[a_row1 * AS_STR + a_q1 * 4 + 3] = f2tf32(pa[1].w);
            *(uint32_t*)&Bn[b_row0 * BS_STR + b_q0 * 4 + 0] = f2tf32(pb[0].x);
            *(uint32_t*)&Bn[b_row0 * BS_STR + b_q0 * 4 + 1] = f2tf32(pb[0].y);
            *(uint32_t*)&Bn[b_row0 * BS_STR + b_q0 * 4 + 2] = f2tf32(pb[0].z);
            *(uint32_t*)&Bn[b_row0 * BS_STR + b_q0 * 4 + 3] = f2tf32(pb[0].w);
            *(uint32_t*)&Bn[b_row1 * BS_STR + b_q1 * 4 + 0] = f2tf32(pb[1].x);
            *(uint32_t*)&Bn[b_row1 * BS_STR + b_q1 * 4 + 1] = f2tf32(pb[1].y);
            *(uint32_t*)&Bn[b_row1 * BS_STR + b_q1 * 4 + 2] = f2tf32(pb[1].z);
            *(uint32_t*)&Bn[b_row1 * BS_STR + b_q1 * 4 + 3] = f2tf32(pb[1].w);
            __syncthreads();
            buf ^= 1;
        }
    }

    // epilogue: bias, Q prescale, tf32 rounding. V written TRANSPOSED [bh][d][n].
#pragma unroll
    for (int mt = 0; mt < 4; mt++) {
#pragma unroll
        for (int nt = 0; nt < 4; nt++) {
            const int j  = n0 + wc * 32 + nt * 8 + tg * 2;
            const int h  = j >> 6, dd = j & 63;
            const float bj0 = bias[j], bj1 = bias[j + 1];
            const int m  = m0 + wr * 64 + mt * 16 + gp;
            const int bb = m >> 11, nn = m & 2047;
            const float r00 = __uint_as_float(f2tf32((c[mt][nt][0] + bj0) * sc));
            const float r01 = __uint_as_float(f2tf32((c[mt][nt][1] + bj1) * sc));
            const float r10 = __uint_as_float(f2tf32((c[mt][nt][2] + bj0) * sc));
            const float r11 = __uint_as_float(f2tf32((c[mt][nt][3] + bj1) * sc));
            if (z == 2) {
                float* bp = outp + (((size_t)(bb * H_ + h)) * D_ + dd) * N_ + nn;
                bp[0]      = r00;   // (dd,   nn)
                bp[N_]     = r01;   // (dd+1, nn)
                bp[8]      = r10;   // (dd,   nn+8)
                bp[N_ + 8] = r11;   // (dd+1, nn+8)
            } else {
                float* bp = outp + (((size_t)(bb * H_ + h)) * N_ + nn) * D_ + dd;
                *(float2*)bp = make_float2(r00, r01);
                *(float2*)(bp + 8 * (size_t)D_) = make_float2(r10, r11);
            }
        }
    }
}

// ---------------------------------------------------------------------------
// tf32 flash attention v4: all staging via cp.async (K rows sigma-permuted at
// copy, V pre-transposed in global), LDSM everywhere, P in registers.
// ---------------------------------------------------------------------------
#define QS_STR 68
#define KS_STR 68
#define VT_STR 68
#define FLASH_SMEM ((128*QS_STR + 2*64*KS_STR + 2*64*VT_STR) * 4)  // 104448 B

__global__ __launch_bounds__(256, 2)
void flash_mma(const float* __restrict__ gq, const float* __restrict__ gk,
               const float* __restrict__ gvt, float* __restrict__ out)
{
    extern __shared__ __align__(16) uint32_t smu[];
    uint32_t* Qs = smu;                       // 128 x 68
    uint32_t* Ks = Qs + 128 * QS_STR;         // 2 x 64 x 68, rows sigma-permuted
    uint32_t* Vt = Ks + 2 * 64 * KS_STR;      // 2 x 64(d) x 68(kv), natural

    const int tid = threadIdx.x, lane = tid & 31, wid = tid >> 5;
    const int gp = lane >> 2, tg = lane & 3;
    const int qt = (int)gridDim.x - 1 - (int)blockIdx.x;  // heavy tiles first
    const int bh = blockIdx.y;
    const int n0 = qt * 128;
    const int nkt = 2 * qt + 2;

    const float* qb = gq  + (size_t)bh * (N_ * D_);
    const float* kb = gk  + (size_t)bh * (N_ * D_);
    const float* vtb = gvt + (size_t)bh * (D_ * N_);   // [d][n]

    const uint32_t qs_base = smem_u32(Qs);
    const uint32_t ks_base = smem_u32(Ks);
    const uint32_t vt_base = smem_u32(Vt);

    // K loader: 4 threads/row; destination row sigma^{-1}-permuted within 8-block
    const int kr = tid >> 2, kc = (tid & 3) * 16;
    const int kr8 = kr & 7;
    const int krow = (kr & ~7) | (kr8 < 4 ? 2 * kr8 : 2 * (kr8 - 4) + 1);
    // V loader: 4 threads/row over d; natural columns (kv)
    const int vr = tid >> 2, vc = (tid & 3) * 16;

    // --- prologue: cp.async Q + K tile0 + Vt tile0 ---
    {
        const int qr = tid >> 1, qc0 = (tid & 1) * 32;
        const float* src = qb + (size_t)(n0 + qr) * D_ + qc0;
        uint32_t dst = qs_base + ((qr * QS_STR + qc0) << 2);
#pragma unroll
        for (int i = 0; i < 8; i++) CP_ASYNC16(dst + 16 * i, src + 4 * i);
    }
    {
        const float* src = kb + (size_t)kr * D_ + kc;
        uint32_t dst = ks_base + ((krow * KS_STR + kc) << 2);
#pragma unroll
        for (int i = 0; i < 4; i++) CP_ASYNC16(dst + 16 * i, src + 4 * i);
    }
    {
        const float* src = vtb + (size_t)vr * N_ + vc;
        uint32_t dst = vt_base + ((vr * VT_STR + vc) << 2);
#pragma unroll
        for (int i = 0; i < 4; i++) CP_ASYNC16(dst + 16 * i, src + 4 * i);
    }
    CP_COMMIT();
    CP_WAIT0();
    __syncthreads();

    // Q fragments via LDSM (held for the whole kernel)
    uint32_t qf[8][4];
    {
        const int qrow = wid * 16 + ((lane >> 3) & 1) * 8 + (lane & 7);
        const int qcol = ((lane >> 4) & 1) * 4;
        const uint32_t qaddr = qs_base + ((qrow * QS_STR + qcol) << 2);
#pragma unroll
        for (int ks = 0; ks < 8; ks++)
            ldsm_x4(qf[ks][0], qf[ks][1], qf[ks][2], qf[ks][3],
                    qaddr + ((ks * 8) << 2));
    }

    // LDSM lane-address pieces (same form for K and Vt)
    const int lrow8 = ((lane >> 4) & 1) * 8 + (lane & 7);
    const int lcol4 = ((lane >> 3) & 1) * 4;

    float m0r = -1e30f, m1r = -1e30f, l0 = 0.f, l1 = 0.f;
    float o[8][4];
#pragma unroll
    for (int nt = 0; nt < 8; nt++)
#pragma unroll
        for (int e = 0; e < 4; e++) o[nt][e] = 0.f;

    int buf = 0;
    for (int kt = 0; kt < nkt; kt++) {
        const int c0 = kt * 64;
        const int more = (kt + 1 < nkt);

        // issue cp.async for K(t+1), Vt(t+1)
        if (more) {
            {
                const float* src = kb + (size_t)(c0 + 64 + kr) * D_ + kc;
                uint32_t dst = ks_base +
                    (((buf ^ 1) * 64 * KS_STR + krow * KS_STR + kc) << 2);
#pragma unroll
                for (int i = 0; i < 4; i++) CP_ASYNC16(dst + 16 * i, src + 4 * i);
            }
            {
                const float* src = vtb + (size_t)vr * N_ + c0 + 64 + vc;
                uint32_t dst = vt_base +
                    (((buf ^ 1) * 64 * VT_STR + vr * VT_STR + vc) << 2);
#pragma unroll
                for (int i = 0; i < 4; i++) CP_ASYNC16(dst + 16 * i, src + 4 * i);
            }
            CP_COMMIT();
        }

        // --- S = Q K^T (columns in sigma-permuted kv order) ---
        float s[8][4];
#pragma unroll
        for (int nt = 0; nt < 8; nt++)
#pragma unroll
            for (int e = 0; e < 4; e++) s[nt][e] = 0.f;

        const uint32_t kaddr = ks_base +
            ((buf * 64 * KS_STR + lrow8 * KS_STR + lcol4) << 2);
#pragma unroll
        for (int n = 0; n < 4; n++) {
            const uint32_t an = kaddr + ((n * 16 * KS_STR) << 2);
#pragma unroll
            for (int ks = 0; ks < 8; ks++) {
                uint32_t b0a, b1a, b0b, b1b;
                ldsm_x4(b0a, b1a, b0b, b1b, an + ((ks * 8) << 2));
                mma_tf32(s[2*n][0], s[2*n][1], s[2*n][2], s[2*n][3],
                         qf[ks][0], qf[ks][1], qf[ks][2], qf[ks][3], b0a, b1a);
                mma_tf32(s[2*n+1][0], s[2*n+1][1], s[2*n+1][2], s[2*n+1][3],
                         qf[ks][0], qf[ks][1], qf[ks][2], qf[ks][3], b0b, b1b);
            }
        }

        // --- causal mask: reg cols {0,1} now hold kv {tg, tg+4} ---
        const int r0 = wid * 16 + gp;
        if (kt >= 2 * qt) {
            const int i0g = n0 + r0, i1g = i0g + 8;
#pragma unroll
            for (int nt = 0; nt < 8; nt++) {
                const int jb = c0 + nt * 8;
                if (jb + tg     > i0g) s[nt][0] = -1e30f;
                if (jb + tg + 4 > i0g) s[nt][1] = -1e30f;
                if (jb + tg     > i1g) s[nt][2] = -1e30f;
                if (jb + tg + 4 > i1g) s[nt][3] = -1e30f;
            }
        }

        // --- online softmax (log2 domain) ---
        float mx0 = -1e30f, mx1 = -1e30f;
#pragma unroll
        for (int nt = 0; nt < 8; nt++) {
            mx0 = fmaxf(mx0, fmaxf(s[nt][0], s[nt][1]));
            mx1 = fmaxf(mx1, fmaxf(s[nt][2], s[nt][3]));
        }
        mx0 = fmaxf(mx0, __shfl_xor_sync(0xffffffffu, mx0, 1));
        mx0 = fmaxf(mx0, __shfl_xor_sync(0xffffffffu, mx0, 2));
        mx1 = fmaxf(mx1, __shfl_xor_sync(0xffffffffu, mx1, 1));
        mx1 = fmaxf(mx1, __shfl_xor_sync(0xffffffffu, mx1, 2));

        const float mn0 = fmaxf(m0r, mx0), mn1 = fmaxf(m1r, mx1);
        const float al0 = ex2f(m0r - mn0), al1 = ex2f(m1r - mn1);
        m0r = mn0; m1r = mn1;

        float ls0 = 0.f, ls1 = 0.f;
#pragma unroll
        for (int nt = 0; nt < 8; nt++) {
            s[nt][0] = ex2f(s[nt][0] - mn0);
            s[nt][1] = ex2f(s[nt][1] - mn0);
            s[nt][2] = ex2f(s[nt][2] - mn1);
            s[nt][3] = ex2f(s[nt][3] - mn1);
            ls0 += s[nt][0] + s[nt][1];
            ls1 += s[nt][2] + s[nt][3];
        }
        ls0 += __shfl_xor_sync(0xffffffffu, ls0, 1);
        ls0 += __shfl_xor_sync(0xffffffffu, ls0, 2);
        ls1 += __shfl_xor_sync(0xffffffffu, ls1, 1);
        ls1 += __shfl_xor_sync(0xffffffffu, ls1, 2);
        l0 = l0 * al0 + ls0;
        l1 = l1 * al1 + ls1;
#pragma unroll
        for (int nt = 0; nt < 8; nt++) {
            o[nt][0] *= al0; o[nt][1] *= al0;
            o[nt][2] *= al1; o[nt][3] *= al1;
        }

        // --- O += P V (P regs directly as a-frags; Vt natural) ---
        const uint32_t vaddr = vt_base +
            ((buf * 64 * VT_STR + lrow8 * VT_STR + lcol4) << 2);
#pragma unroll
        for (int ks = 0; ks < 8; ks++) {
            const uint32_t a0 = f2tf32(s[ks][0]);
            const uint32_t a1 = f2tf32(s[ks][2]);
            const uint32_t a2 = f2tf32(s[ks][1]);
            const uint32_t a3 = f2tf32(s[ks][3]);
#pragma unroll
            for (int n = 0; n < 4; n++) {
                uint32_t b0a, b1a, b0b, b1b;
                ldsm_x4(b0a, b1a, b0b, b1b,
                        vaddr + ((n * 16 * VT_STR + ks * 8) << 2));
                mma_tf32(o[2*n][0], o[2*n][1], o[2*n][2], o[2*n][3],
                         a0, a1, a2, a3, b0a, b1a);
                mma_tf32(o[2*n+1][0], o[2*n+1][1], o[2*n+1][2], o[2*n+1][3],
                         a0, a1, a2, a3, b0b, b1b);
            }
        }

        // --- wait staged tiles; flip ---
        if (more) {
            CP_WAIT0();
            __syncthreads();
            buf ^= 1;
        }
    }

    // --- normalize and write out [B, N, F] ---
    const int r0 = wid * 16 + gp;
    const float inv0 = 1.f / l0, inv1 = 1.f / l1;
    const int bb = bh >> 4, h = bh & 15;
    float* base = out + ((size_t)(bb * N_ + n0 + r0)) * F_ + h * D_;
#pragma unroll
    for (int nt = 0; nt < 8; nt++) {
        const int d = nt * 8 + 2 * tg;
        *(float2*)(base + d) = make_float2(o[nt][0] * inv0, o[nt][1] * inv0);
        *(float2*)(base + 8 * F_ + d) = make_float2(o[nt][2] * inv1, o[nt][3] * inv1);
    }
}

// ---------------------------------------------------------------------------
extern "C" void kernel_launch(void* const* d_in, const int* in_sizes, int n_in,
                              void* d_out, int out_size)
{
    const float* x  = (const float*)d_in[0];
    const float* Wq = (const float*)d_in[1];
    const float* bq = (const float*)d_in[2];
    const float* Wk = (const float*)d_in[3];
    const float* bk = (const float*)d_in[4];
    const float* Wv = (const float*)d_in[5];
    const float* bv = (const float*)d_in[6];
    float* out = (float*)d_out;
    (void)in_sizes; (void)n_in; (void)out_size;

    float *pq = nullptr, *pk = nullptr, *pv = nullptr;
    cudaGetSymbolAddress((void**)&pq, g_q);
    cudaGetSymbolAddress((void**)&pk, g_k);
    cudaGetSymbolAddress((void**)&pv, g_v);

    qkv_mma_gemm<<<dim3(F_ / 128, M_ / 128, 3), 256>>>(
        x, Wq, Wk, Wv, bq, bk, bv, pq, pk, pv);

    cudaFuncSetAttribute(flash_mma,
                         cudaFuncAttributeMaxDynamicSharedMemorySize, FLASH_SMEM);
    flash_mma<<<dim3(N_ / 128, B_ * H_), 256, FLASH_SMEM>>>(pq, pk, pv, out);
}